// round 9
// baseline (speedup 1.0000x reference)
#include <cuda_runtime.h>
#include <cuda_bf16.h>
#include <math.h>
#include <stddef.h>
#include <stdint.h>

#define NB 4
#define NS 2048
#define NC 640
#define NH 10
#define ND 64

// log2(e) * attn_scale(0.125): folded into adain coeffs; softmax uses ex2
#define QSCALE 0.1803368801111204f

// ---------------- device scratch (no allocs allowed) ----------------
__device__ __nv_bfloat16 g_hsb[(size_t)NB * NS * NC];
__device__ __nv_bfloat16 g_wqb[NC * NC];
__device__ __nv_bfloat16 g_wkb[NC * NC];
__device__ __nv_bfloat16 g_wvb[NC * NC];
__device__ __nv_bfloat16 g_wob[NC * NC];
__device__ __nv_bfloat16 g_qb [(size_t)NB * NS * NC];   // q bf16 (raw projection)
__device__ __nv_bfloat16 g_kb [(size_t)2  * NS * NC];   // k bf16 (batches 0,2)
__device__ __nv_bfloat16 g_vb [(size_t)2  * NS * NC];
__device__ __nv_bfloat16 g_ob [(size_t)NB * NS * NC];   // attention out bf16
__device__ float g_ps[64 * NC];    // partial sums   (4 b x 16 chunks of 128 rows)
__device__ float g_pq[64 * NC];    // partial sq-sums
__device__ float g_A[NB * NC];     // per-(b,channel) affine scale (incl QSCALE)
__device__ float g_B[NB * NC];     // per-(b,channel) affine bias  (incl QSCALE)

// ---------------- PTX helpers (baseline sm_80+, safe on sm_100) ------------
__device__ __forceinline__ uint32_t smem_u32(const void* p) {
    uint32_t a;
    asm("{ .reg .u64 t; cvta.to.shared.u64 t, %1; cvt.u32.u64 %0, t; }" : "=r"(a) : "l"(p));
    return a;
}

#define CP16(dst, src) \
    asm volatile("cp.async.cg.shared.global [%0], [%1], 16;" :: "r"(dst), "l"(src))
#define CP_COMMIT() asm volatile("cp.async.commit_group;" ::: "memory")
#define CP_WAIT1()  asm volatile("cp.async.wait_group 1;" ::: "memory")

__device__ __forceinline__ void ldm_x4(uint32_t& r0, uint32_t& r1, uint32_t& r2, uint32_t& r3, uint32_t a) {
    asm volatile("ldmatrix.sync.aligned.m8n8.x4.shared.b16 {%0,%1,%2,%3}, [%4];"
        : "=r"(r0), "=r"(r1), "=r"(r2), "=r"(r3) : "r"(a));
}
__device__ __forceinline__ void ldm_x4t(uint32_t& r0, uint32_t& r1, uint32_t& r2, uint32_t& r3, uint32_t a) {
    asm volatile("ldmatrix.sync.aligned.m8n8.x4.trans.shared.b16 {%0,%1,%2,%3}, [%4];"
        : "=r"(r0), "=r"(r1), "=r"(r2), "=r"(r3) : "r"(a));
}
__device__ __forceinline__ void mma_bf16(float* c, const uint32_t* a,
                                         uint32_t b0, uint32_t b1) {
    asm volatile("mma.sync.aligned.m16n8k16.row.col.f32.bf16.bf16.f32 "
        "{%0,%1,%2,%3}, {%4,%5,%6,%7}, {%8,%9}, {%0,%1,%2,%3};"
        : "+f"(c[0]), "+f"(c[1]), "+f"(c[2]), "+f"(c[3])
        : "r"(a[0]), "r"(a[1]), "r"(a[2]), "r"(a[3]), "r"(b0), "r"(b1));
}
__device__ __forceinline__ uint32_t packbf(float lo, float hi) {
    __nv_bfloat162 p = __floats2bfloat162_rn(lo, hi);
    return *(uint32_t*)&p;
}
__device__ __forceinline__ float ex2f(float x) {
    float r;
    asm("ex2.approx.ftz.f32 %0, %1;" : "=f"(r) : "f"(x));
    return r;
}
__device__ __forceinline__ float bf2f(uint16_t u) {
    __nv_bfloat16 h = *(__nv_bfloat16*)&u;
    return __bfloat162float(h);
}

// ---------------- merged fp32 -> bf16 convert (hs + 4 weights) -------------
__global__ void __launch_bounds__(256) conv_all(
    const float* __restrict__ hs, const float* __restrict__ wq,
    const float* __restrict__ wk, const float* __restrict__ wv,
    const float* __restrict__ wo,
    __nv_bfloat16* __restrict__ hsb, __nv_bfloat16* __restrict__ wqb,
    __nv_bfloat16* __restrict__ wkb, __nv_bfloat16* __restrict__ wvb,
    __nv_bfloat16* __restrict__ wob)
{
    int blk = blockIdx.x;
    const float* src; __nv_bfloat16* dst; int base;
    if (blk < 5120) { src = hs; dst = hsb; base = blk; }
    else {
        int t = blk - 5120, w = t / 400;
        base = t % 400;
        src = (w == 0) ? wq : (w == 1) ? wk : (w == 2) ? wv : wo;
        dst = (w == 0) ? wqb : (w == 1) ? wkb : (w == 2) ? wvb : wob;
    }
    int i = base * 256 + threadIdx.x;
    float4 v = ((const float4*)src)[i];
    uint2 o;
    o.x = packbf(v.x, v.y);
    o.y = packbf(v.z, v.w);
    ((uint2*)dst)[i] = o;
}

// ---------------- GEMM: C[M,640] = A[M,640] @ W[640,640]^T ------------------
// MODE 2: fp32 out + bias + residual (final projection), grid (5, 64); W=Wk slot.
// MODE 5: merged QKV. grid (10, 64):
//   by <  32 : K/V path (rows remapped to source batches {0,2}):
//              bx<5 -> Wk/outK else Wv/outV; col0=(bx%5)*128; row0=by*128
//   by >= 32 : Q path: Wq/outQ; col0=(bx%5)*128; row0=((by-32)*2+(bx/5))*128
//              + fused AdaIN stats pass 1: per-block column sums/sq-sums of the
//              fp32 tile -> g_ps/g_pq[(row0>>7)*NC + col0 + c]
// 128x128 block, BK=32, 256 threads (8 warps, each 32x64), cp.async 2-stage.
template <int MODE>
__global__ void __launch_bounds__(256) gemm_mma(
    const __nv_bfloat16* __restrict__ Ain,
    const __nv_bfloat16* __restrict__ Wk, const __nv_bfloat16* __restrict__ Wv,
    const __nv_bfloat16* __restrict__ Wq,
    const float* __restrict__ bias, const float* __restrict__ resid,
    float* __restrict__ outF,
    __nv_bfloat16* __restrict__ outK, __nv_bfloat16* __restrict__ outV,
    __nv_bfloat16* __restrict__ outQ,
    float* __restrict__ ps, float* __restrict__ pq)
{
    __shared__ __align__(16) char smem[40960];   // 2 stages x (A 10240 + B 10240)
    const uint32_t sb = smem_u32(smem);
    const int tid = threadIdx.x;
    const int w = tid >> 5, lam = tid & 31;

    const __nv_bfloat16* W;
    __nv_bfloat16* outB = nullptr;
    int row0, col0;
    bool remap = false, qpath = false;
    if (MODE == 5) {
        int bx = blockIdx.x, by = blockIdx.y;
        col0 = (bx % 5) * 128;
        if (by < 32) {
            W = (bx < 5) ? Wk : Wv;
            outB = (bx < 5) ? outK : outV;
            row0 = by * 128;
            remap = true;
        } else {
            W = Wq; outB = outQ;
            row0 = ((by - 32) * 2 + (bx / 5)) * 128;
            qpath = true;
        }
    } else {
        W = Wk;
        row0 = blockIdx.y * 128; col0 = blockIdx.x * 128;
    }

    const int warp_m = (w & 3) * 32, warp_n = (w >> 2) * 64;

    const int lrow = tid >> 1;
    const int gr = row0 + lrow;
    const int arow = remap ? ((gr & 2047) + ((gr >> 11) << 12)) : gr;
    const char* ag = (const char*)(Ain + (size_t)arow * NC) + (tid & 1) * 32;
    const char* bg = (const char*)(W + (size_t)(col0 + lrow) * NC) + (tid & 1) * 32;
    const uint32_t asb = sb + lrow * 80 + (tid & 1) * 32;
    const uint32_t bsb = sb + 10240 + lrow * 80 + (tid & 1) * 32;

    float acc[2][8][4];
#pragma unroll
    for (int i = 0; i < 2; i++)
#pragma unroll
        for (int j = 0; j < 8; j++)
#pragma unroll
            for (int e = 0; e < 4; e++) acc[i][j][e] = 0.f;

#pragma unroll
    for (int s = 0; s < 2; s++) {
        uint32_t so = s * 20480;
        int kb_ = s * 64;
        CP16(asb + so, ag + kb_); CP16(asb + so + 16, ag + kb_ + 16);
        CP16(bsb + so, bg + kb_); CP16(bsb + so + 16, bg + kb_ + 16);
        CP_COMMIT();
    }

    for (int c = 0; c < 20; c++) {
        CP_WAIT1(); __syncthreads();
        const int st = c & 1;
        const uint32_t sa  = sb + st * 20480;
        const uint32_t sbm = sb + 10240 + st * 20480;
        const uint32_t aab = sa + (warp_m + (lam & 15)) * 80 + (lam >> 4) * 16;
        const uint32_t bab4 = sbm + (warp_n + (lam & 7) + ((lam >> 4) << 3)) * 80
                              + ((lam >> 3) & 1) * 16;
#pragma unroll
        for (int s = 0; s < 2; s++) {
            uint32_t a0[4], a1[4];
            ldm_x4(a0[0], a0[1], a0[2], a0[3], aab + s * 32);
            ldm_x4(a1[0], a1[1], a1[2], a1[3], aab + 16 * 80 + s * 32);
#pragma unroll
            for (int jp = 0; jp < 4; jp++) {
                uint32_t b0, b1, b2, b3;
                ldm_x4(b0, b1, b2, b3, bab4 + jp * (16 * 80) + s * 32);
                mma_bf16(acc[0][2 * jp],     a0, b0, b1);
                mma_bf16(acc[0][2 * jp + 1], a0, b2, b3);
                mma_bf16(acc[1][2 * jp],     a1, b0, b1);
                mma_bf16(acc[1][2 * jp + 1], a1, b2, b3);
            }
        }
        __syncthreads();
        if (c + 2 < 20) {
            uint32_t so = st * 20480;
            int kb_ = (c + 2) * 64;
            CP16(asb + so, ag + kb_); CP16(asb + so + 16, ag + kb_ + 16);
            CP16(bsb + so, bg + kb_); CP16(bsb + so + 16, bg + kb_ + 16);
        }
        CP_COMMIT();
    }

    const int rb = row0 + warp_m + (lam >> 2);
    const int cb = col0 + warp_n + 2 * (lam & 3);
#pragma unroll
    for (int im = 0; im < 2; im++) {
#pragma unroll
        for (int j = 0; j < 8; j++) {
            int r = rb + im * 16;
            int cc = cb + j * 8;
            float* a4 = acc[im][j];
            if (MODE == 2) {
                size_t o0 = (size_t)r * NC + cc;
                size_t o1 = (size_t)(r + 8) * NC + cc;
                float2 rv0 = *(const float2*)(resid + o0);
                float2 rv1 = *(const float2*)(resid + o1);
                float2 bv = *(const float2*)(bias + cc);
                *(float2*)(outF + o0) = make_float2(a4[0] + bv.x + rv0.x, a4[1] + bv.y + rv0.y);
                *(float2*)(outF + o1) = make_float2(a4[2] + bv.x + rv1.x, a4[3] + bv.y + rv1.y);
            } else {
                *(uint32_t*)(outB + (size_t)r * NC + cc) = packbf(a4[0], a4[1]);
                *(uint32_t*)(outB + (size_t)(r + 8) * NC + cc) = packbf(a4[2], a4[3]);
            }
        }
    }

    // ---- fused AdaIN stats pass 1 (Q path only) ----
    if (MODE == 5 && qpath) {
        float cs[16], cq[16];
#pragma unroll
        for (int j = 0; j < 8; j++) {
            float slo = 0.f, shi = 0.f, qlo = 0.f, qhi = 0.f;
#pragma unroll
            for (int im = 0; im < 2; im++) {
                float a0 = acc[im][j][0], a1 = acc[im][j][1];
                float a2 = acc[im][j][2], a3 = acc[im][j][3];
                slo += a0 + a2;           shi += a1 + a3;
                qlo += a0 * a0 + a2 * a2; qhi += a1 * a1 + a3 * a3;
            }
            // reduce across the 8 row-groups (lane strides 4, 8, 16)
#pragma unroll
            for (int off = 4; off < 32; off <<= 1) {
                slo += __shfl_xor_sync(0xffffffffu, slo, off);
                shi += __shfl_xor_sync(0xffffffffu, shi, off);
                qlo += __shfl_xor_sync(0xffffffffu, qlo, off);
                qhi += __shfl_xor_sync(0xffffffffu, qhi, off);
            }
            cs[2 * j] = slo; cs[2 * j + 1] = shi;
            cq[2 * j] = qlo; cq[2 * j + 1] = qhi;
        }
        // overlay reduction buffers on stage-0 A-tile (dead after chunk 18;
        // chunk-19 reads hit stage 1 @20480+, disjoint from [0, 4096))
        float* sS = (float*)smem;            // [4][128]
        float* sQ = (float*)(smem + 2048);   // [4][128]
        if (lam < 4) {
#pragma unroll
            for (int j = 0; j < 8; j++) {
                int cidx = warp_n + j * 8 + 2 * lam;
                sS[(w & 3) * 128 + cidx]     = cs[2 * j];
                sS[(w & 3) * 128 + cidx + 1] = cs[2 * j + 1];
                sQ[(w & 3) * 128 + cidx]     = cq[2 * j];
                sQ[(w & 3) * 128 + cidx + 1] = cq[2 * j + 1];
            }
        }
        __syncthreads();
        if (tid < 128) {
            float S = sS[tid] + sS[128 + tid] + sS[256 + tid] + sS[384 + tid];
            float Q = sQ[tid] + sQ[128 + tid] + sQ[256 + tid] + sQ[384 + tid];
            int chunk = row0 >> 7;           // 0..63
            ps[chunk * NC + col0 + tid] = S;
            pq[chunk * NC + col0 + tid] = Q;
        }
    }
}

// ------------- AdaIN stats pass 2: warp-parallel finalize -> affine coeffs --
__global__ void __launch_bounds__(256) adain_p2(
    const float* __restrict__ ps, const float* __restrict__ pq,
    float* __restrict__ Ac, float* __restrict__ Bc)
{
    const int wg   = (blockIdx.x << 3) | (threadIdx.x >> 5);   // 0..319
    const int lane = threadIdx.x & 31;
    const int pair = wg / 160;                 // 0..1
    const int c4   = (wg % 160) * 4;
    const int bs = pair * 2, bo = bs + 1;

    float acc[16];
#pragma unroll
    for (int e = 0; e < 16; e++) acc[e] = 0.f;

    if (lane < 16) {
        int j = lane;                          // chunk within batch (16 per batch)
        float4 v;
        v = *(const float4*)(ps + (size_t)(bs * 16 + j) * NC + c4);
        acc[0] = v.x; acc[1] = v.y; acc[2] = v.z; acc[3] = v.w;
        v = *(const float4*)(pq + (size_t)(bs * 16 + j) * NC + c4);
        acc[4] = v.x; acc[5] = v.y; acc[6] = v.z; acc[7] = v.w;
        v = *(const float4*)(ps + (size_t)(bo * 16 + j) * NC + c4);
        acc[8] = v.x; acc[9] = v.y; acc[10] = v.z; acc[11] = v.w;
        v = *(const float4*)(pq + (size_t)(bo * 16 + j) * NC + c4);
        acc[12] = v.x; acc[13] = v.y; acc[14] = v.z; acc[15] = v.w;
    }
#pragma unroll
    for (int off = 16; off; off >>= 1)
#pragma unroll
        for (int e = 0; e < 16; e++)
            acc[e] += __shfl_xor_sync(0xffffffffu, acc[e], off);

    if (lane == 0) {
#pragma unroll
        for (int e = 0; e < 4; e++) {
            float Ssrc = acc[e], Qsrc = acc[4 + e];
            float Sown = acc[8 + e], Qown = acc[12 + e];
            float ms   = Ssrc / (float)NS;
            float vs   = (Qsrc - Ssrc * ms) / (float)(NS - 1);
            float sds  = sqrtf(vs + 1e-5f);
            float mo   = Sown / (float)NS;
            float vo   = (Qown - Sown * mo) / (float)(NS - 1);
            float sdo  = sqrtf(vo + 1e-5f);
            float r = sds / sdo;
            Ac[bs * NC + c4 + e] = QSCALE;
            Bc[bs * NC + c4 + e] = 0.f;
            Ac[bo * NC + c4 + e] = QSCALE * r;
            Bc[bo * NC + c4 + e] = QSCALE * (ms - mo * r);
        }
    }
}

// ---------------- Flash attention via mma.sync ------------------------------
// Block: 64 q-rows of one (b,h), 128 threads (4 warps x 16 rows). BK=64.
// 4 CTAs/SM (fine-grained CTAs halve the wave-quantization tax of the old
// 640-CTA/296-slot grid). AdaIN-apply fused into Q smem staging.
// 2-stage cp.async KV pipeline. No-max base-2 softmax.
__global__ void __launch_bounds__(128, 4) attn_mma(
    const __nv_bfloat16* __restrict__ q, const __nv_bfloat16* __restrict__ k,
    const __nv_bfloat16* __restrict__ v, __nv_bfloat16* __restrict__ o,
    const float* __restrict__ Ac, const float* __restrict__ Bc)
{
    extern __shared__ __align__(16) char smd[];
    // Q 64x144B @0 (9216); stage s (0..1): K @9216+s*18432, V @+9216
    const uint32_t sb = smem_u32(smd);
    const int tid = threadIdx.x, w = tid >> 5, lam = tid & 31;
    const int by = blockIdx.y;
    const int b = by / NH, h = by % NH, kb = b >> 1;
    const int q0 = blockIdx.x * 64;

    // KV loader: row = tid>>1 (0..63), half = (tid&1)*64 bytes, 4 CP16 each
    const int kvrow = tid >> 1, kvhalf = (tid & 1) * 64;
    const char* kg = (const char*)(k + ((size_t)kb * NS + kvrow) * NC + h * 64) + kvhalf;
    const char* vg = (const char*)(v + ((size_t)kb * NS + kvrow) * NC + h * 64) + kvhalf;
    const uint32_t ksb = sb + 9216 + kvrow * 144 + kvhalf;
    const uint32_t vsb = ksb + 9216;
    const size_t kv_step = (size_t)64 * NC * 2;

    // prologue: KV tile0 (stage0), tile1 (stage1)
#pragma unroll
    for (int t = 0; t < 4; t++) { CP16(ksb + t * 16, kg + t * 16); }
#pragma unroll
    for (int t = 0; t < 4; t++) { CP16(vsb + t * 16, vg + t * 16); }
    CP_COMMIT();
#pragma unroll
    for (int t = 0; t < 4; t++) { CP16(ksb + 18432 + t * 16, kg + kv_step + t * 16); }
#pragma unroll
    for (int t = 0; t < 4; t++) { CP16(vsb + 18432 + t * 16, vg + kv_step + t * 16); }
    CP_COMMIT();

    // Q stage with fused AdaIN affine (x*A + B): row = tid>>1 (0..63), half tid&1
    {
        const int row = tid >> 1, half = tid & 1;
        const uint4* qsrc = (const uint4*)((const char*)(q + ((size_t)b * NS + q0 + row) * NC + h * 64) + half * 64);
        const float* Abp = Ac + b * NC + h * 64 + half * 32;
        const float* Bbp = Bc + b * NC + h * 64 + half * 32;
        char* qdst = smd + row * 144 + half * 64;
#pragma unroll
        for (int i = 0; i < 4; i++) {
            uint4 u = qsrc[i];
            float4 A0 = *(const float4*)(Abp + i * 8);
            float4 A1 = *(const float4*)(Abp + i * 8 + 4);
            float4 B0 = *(const float4*)(Bbp + i * 8);
            float4 B1 = *(const float4*)(Bbp + i * 8 + 4);
            uint16_t* e = (uint16_t*)&u;
            uint4 ov;
            ov.x = packbf(bf2f(e[0]) * A0.x + B0.x, bf2f(e[1]) * A0.y + B0.y);
            ov.y = packbf(bf2f(e[2]) * A0.z + B0.z, bf2f(e[3]) * A0.w + B0.w);
            ov.z = packbf(bf2f(e[4]) * A1.x + B1.x, bf2f(e[5]) * A1.y + B1.y);
            ov.w = packbf(bf2f(e[6]) * A1.z + B1.z, bf2f(e[7]) * A1.w + B1.w);
            *(uint4*)(qdst + i * 16) = ov;
        }
    }
    CP_WAIT1(); __syncthreads();

    uint32_t aq[4][4];
    {
        uint32_t qab = sb + (w * 16 + (lam & 15)) * 144 + (lam >> 4) * 16;
#pragma unroll
        for (int t = 0; t < 4; t++)
            ldm_x4(aq[t][0], aq[t][1], aq[t][2], aq[t][3], qab + t * 32);
    }

    float oacc[8][4];
#pragma unroll
    for (int j = 0; j < 8; j++)
#pragma unroll
        for (int e = 0; e < 4; e++) oacc[j][e] = 0.f;
    float l0 = 0.f, l1 = 0.f;

    const uint32_t kab0 = sb + 9216 + ((lam & 7) + ((lam >> 4) << 3)) * 144
                          + ((lam >> 3) & 1) * 16;
    const uint32_t vab0 = sb + 9216 + 9216 + (lam & 15) * 144 + (lam >> 4) * 16;

    for (int i = 0; i < 32; i++) {
        const int st = i & 1;
        const uint32_t kab = kab0 + st * 18432;
        const uint32_t vab = vab0 + st * 18432;

        // S = Q @ K^T : c[j] covers kv cols 8j..8j+7
        float c[8][4];
#pragma unroll
        for (int j = 0; j < 8; j++)
#pragma unroll
            for (int e = 0; e < 4; e++) c[j][e] = 0.f;
#pragma unroll
        for (int t = 0; t < 4; t++) {
#pragma unroll
            for (int jp = 0; jp < 4; jp++) {
                uint32_t b0, b1, b2, b3;
                ldm_x4(b0, b1, b2, b3, kab + jp * (16 * 144) + t * 32);
                mma_bf16(c[2 * jp],     aq[t], b0, b1);
                mma_bf16(c[2 * jp + 1], aq[t], b2, b3);
            }
        }
        float p0 = 0.f, p1 = 0.f;
#pragma unroll
        for (int j = 0; j < 8; j++) {
            c[j][0] = ex2f(c[j][0]); c[j][1] = ex2f(c[j][1]);
            c[j][2] = ex2f(c[j][2]); c[j][3] = ex2f(c[j][3]);
            p0 += c[j][0] + c[j][1];
            p1 += c[j][2] + c[j][3];
        }
        l0 += p0; l1 += p1;
        uint32_t ap[4][4];
#pragma unroll
        for (int t = 0; t < 4; t++) {
            ap[t][0] = packbf(c[2*t][0],   c[2*t][1]);
            ap[t][1] = packbf(c[2*t][2],   c[2*t][3]);
            ap[t][2] = packbf(c[2*t+1][0], c[2*t+1][1]);
            ap[t][3] = packbf(c[2*t+1][2], c[2*t+1][3]);
        }
#pragma unroll
        for (int t = 0; t < 4; t++) {
#pragma unroll
            for (int jp = 0; jp < 4; jp++) {
                uint32_t b0, b1, b2, b3;
                ldm_x4t(b0, b1, b2, b3, vab + t * (16 * 144) + jp * 32);
                mma_bf16(oacc[2 * jp],     ap[t], b0, b1);
                mma_bf16(oacc[2 * jp + 1], ap[t], b2, b3);
            }
        }
        __syncthreads();
        if (i + 2 < 32) {
            const char* kgi = kg + (size_t)(i + 2) * kv_step;
            const char* vgi = vg + (size_t)(i + 2) * kv_step;
            uint32_t ko = ksb + st * 18432, vo = vsb + st * 18432;
#pragma unroll
            for (int t = 0; t < 4; t++) { CP16(ko + t * 16, kgi + t * 16); }
#pragma unroll
            for (int t = 0; t < 4; t++) { CP16(vo + t * 16, vgi + t * 16); }
        }
        CP_COMMIT();
        CP_WAIT1(); __syncthreads();
    }

    l0 += __shfl_xor_sync(0xffffffffu, l0, 1);
    l0 += __shfl_xor_sync(0xffffffffu, l0, 2);
    l1 += __shfl_xor_sync(0xffffffffu, l1, 1);
    l1 += __shfl_xor_sync(0xffffffffu, l1, 2);
    const float i0 = 1.f / l0, i1 = 1.f / l1;

    const int r = q0 + w * 16 + (lam >> 2);
    __nv_bfloat16* ob0 = o + ((size_t)b * NS + r) * NC + h * 64 + 2 * (lam & 3);
#pragma unroll
    for (int j = 0; j < 8; j++) {
        *(uint32_t*)(ob0 + j * 8)          = packbf(oacc[j][0] * i0, oacc[j][1] * i0);
        *(uint32_t*)(ob0 + 8 * NC + j * 8) = packbf(oacc[j][2] * i1, oacc[j][3] * i1);
    }
}

// ---------------- launch ----------------
extern "C" void kernel_launch(void* const* d_in, const int* in_sizes, int n_in,
                              void* d_out, int out_size)
{
    const float* hs = (const float*)d_in[0];
    const float* wq = (const float*)d_in[1];
    const float* wk = (const float*)d_in[2];
    const float* wv = (const float*)d_in[3];
    const float* wo = (const float*)d_in[4];
    const float* bo = (const float*)d_in[5];
    float* out = (float*)d_out;

    __nv_bfloat16 *hsb, *wqb, *wkb, *wvb, *wob, *qb, *kbp, *vbp, *obp;
    float *ps, *pq, *Ac, *Bc;
    cudaGetSymbolAddress((void**)&hsb, g_hsb);
    cudaGetSymbolAddress((void**)&wqb, g_wqb);
    cudaGetSymbolAddress((void**)&wkb, g_wkb);
    cudaGetSymbolAddress((void**)&wvb, g_wvb);
    cudaGetSymbolAddress((void**)&wob, g_wob);
    cudaGetSymbolAddress((void**)&qb,  g_qb);
    cudaGetSymbolAddress((void**)&kbp, g_kb);
    cudaGetSymbolAddress((void**)&vbp, g_vb);
    cudaGetSymbolAddress((void**)&obp, g_ob);
    cudaGetSymbolAddress((void**)&ps,  g_ps);
    cudaGetSymbolAddress((void**)&pq,  g_pq);
    cudaGetSymbolAddress((void**)&Ac,  g_A);
    cudaGetSymbolAddress((void**)&Bc,  g_B);

    const int ATTN_SMEM = 9216 + 2 * 18432;    // 46080
    cudaFuncSetAttribute(attn_mma, cudaFuncAttributeMaxDynamicSharedMemorySize, ATTN_SMEM);

    // one merged convert (hs + 4 weights)
    conv_all<<<6720, 256>>>(hs, wq, wk, wv, wo, hsb, wqb, wkb, wvb, wob);

    // merged Q + K + V projections (K/V from source batches 0,2 only)
    // + fused AdaIN stats pass 1 in the Q-path epilogue
    gemm_mma<5><<<dim3(10, 64), 256>>>(hsb, wkb, wvb, wqb, nullptr, nullptr,
                                       nullptr, kbp, vbp, qb, ps, pq);

    // AdaIN stats finalize (warp-parallel) -> affine coeffs
    adain_p2<<<40, 256>>>(ps, pq, Ac, Bc);

    // attention with fused AdaIN-apply on Q (fine-grained 64-row CTAs)
    attn_mma<<<dim3(32, 40), 128, ATTN_SMEM>>>(qb, kbp, vbp, obp, Ac, Bc);

    // output projection + bias + residual (fp32)
    gemm_mma<2><<<dim3(5, 64), 256>>>(obp, wob, nullptr, nullptr, bo, hs,
                                      out, nullptr, nullptr, nullptr, nullptr, nullptr);
}

// round 10
// speedup vs baseline: 1.1181x; 1.1181x over previous
#include <cuda_runtime.h>
#include <cuda_bf16.h>
#include <math.h>
#include <stddef.h>
#include <stdint.h>

#define NB 4
#define NS 2048
#define NC 640
#define NH 10
#define ND 64

// log2(e) * attn_scale(0.125): folded into adain coeffs; softmax uses ex2
#define QSCALE 0.1803368801111204f

// ---------------- device scratch (no allocs allowed) ----------------
__device__ __nv_bfloat16 g_hsb[(size_t)NB * NS * NC];
__device__ __nv_bfloat16 g_wqb[NC * NC];
__device__ __nv_bfloat16 g_wkb[NC * NC];
__device__ __nv_bfloat16 g_wvb[NC * NC];
__device__ __nv_bfloat16 g_wob[NC * NC];
__device__ __nv_bfloat16 g_qb [(size_t)NB * NS * NC];   // q bf16 (raw projection)
__device__ __nv_bfloat16 g_kb [(size_t)2  * NS * NC];   // k bf16 (batches 0,2)
__device__ __nv_bfloat16 g_vb [(size_t)2  * NS * NC];
__device__ __nv_bfloat16 g_os0[(size_t)NB * NS * NC];   // split-KV partial O (half 0)
__device__ __nv_bfloat16 g_os1[(size_t)NB * NS * NC];   // split-KV partial O (half 1)
__device__ float g_l0[NB * NH * NS];                    // split-KV partial l
__device__ float g_l1[NB * NH * NS];
__device__ __nv_bfloat16 g_ob [(size_t)NB * NS * NC];   // attention out bf16
__device__ float g_ps[64 * NC];    // partial sums   (4 b x 16 chunks of 128 rows)
__device__ float g_pq[64 * NC];    // partial sq-sums
__device__ float g_A[NB * NC];     // per-(b,channel) affine scale (incl QSCALE)
__device__ float g_B[NB * NC];     // per-(b,channel) affine bias  (incl QSCALE)

// ---------------- PTX helpers (baseline sm_80+, safe on sm_100) ------------
__device__ __forceinline__ uint32_t smem_u32(const void* p) {
    uint32_t a;
    asm("{ .reg .u64 t; cvta.to.shared.u64 t, %1; cvt.u32.u64 %0, t; }" : "=r"(a) : "l"(p));
    return a;
}

#define CP16(dst, src) \
    asm volatile("cp.async.cg.shared.global [%0], [%1], 16;" :: "r"(dst), "l"(src))
#define CP_COMMIT() asm volatile("cp.async.commit_group;" ::: "memory")
#define CP_WAIT1()  asm volatile("cp.async.wait_group 1;" ::: "memory")

__device__ __forceinline__ void ldm_x4(uint32_t& r0, uint32_t& r1, uint32_t& r2, uint32_t& r3, uint32_t a) {
    asm volatile("ldmatrix.sync.aligned.m8n8.x4.shared.b16 {%0,%1,%2,%3}, [%4];"
        : "=r"(r0), "=r"(r1), "=r"(r2), "=r"(r3) : "r"(a));
}
__device__ __forceinline__ void ldm_x4t(uint32_t& r0, uint32_t& r1, uint32_t& r2, uint32_t& r3, uint32_t a) {
    asm volatile("ldmatrix.sync.aligned.m8n8.x4.trans.shared.b16 {%0,%1,%2,%3}, [%4];"
        : "=r"(r0), "=r"(r1), "=r"(r2), "=r"(r3) : "r"(a));
}
__device__ __forceinline__ void mma_bf16(float* c, const uint32_t* a,
                                         uint32_t b0, uint32_t b1) {
    asm volatile("mma.sync.aligned.m16n8k16.row.col.f32.bf16.bf16.f32 "
        "{%0,%1,%2,%3}, {%4,%5,%6,%7}, {%8,%9}, {%0,%1,%2,%3};"
        : "+f"(c[0]), "+f"(c[1]), "+f"(c[2]), "+f"(c[3])
        : "r"(a[0]), "r"(a[1]), "r"(a[2]), "r"(a[3]), "r"(b0), "r"(b1));
}
__device__ __forceinline__ uint32_t packbf(float lo, float hi) {
    __nv_bfloat162 p = __floats2bfloat162_rn(lo, hi);
    return *(uint32_t*)&p;
}
__device__ __forceinline__ float ex2f(float x) {
    float r;
    asm("ex2.approx.ftz.f32 %0, %1;" : "=f"(r) : "f"(x));
    return r;
}
__device__ __forceinline__ float bf2f(uint16_t u) {
    __nv_bfloat16 h = *(__nv_bfloat16*)&u;
    return __bfloat162float(h);
}

// ---------------- merged fp32 -> bf16 convert (hs + 4 weights) -------------
__global__ void __launch_bounds__(256) conv_all(
    const float* __restrict__ hs, const float* __restrict__ wq,
    const float* __restrict__ wk, const float* __restrict__ wv,
    const float* __restrict__ wo,
    __nv_bfloat16* __restrict__ hsb, __nv_bfloat16* __restrict__ wqb,
    __nv_bfloat16* __restrict__ wkb, __nv_bfloat16* __restrict__ wvb,
    __nv_bfloat16* __restrict__ wob)
{
    int blk = blockIdx.x;
    const float* src; __nv_bfloat16* dst; int base;
    if (blk < 5120) { src = hs; dst = hsb; base = blk; }
    else {
        int t = blk - 5120, w = t / 400;
        base = t % 400;
        src = (w == 0) ? wq : (w == 1) ? wk : (w == 2) ? wv : wo;
        dst = (w == 0) ? wqb : (w == 1) ? wkb : (w == 2) ? wvb : wob;
    }
    int i = base * 256 + threadIdx.x;
    float4 v = ((const float4*)src)[i];
    uint2 o;
    o.x = packbf(v.x, v.y);
    o.y = packbf(v.z, v.w);
    ((uint2*)dst)[i] = o;
}

// ---------------- GEMM: C[M,640] = A[M,640] @ W[640,640]^T ------------------
// MODE 2: fp32 out + bias + residual (final projection), grid (5, 64); W=Wk slot.
// MODE 5: merged QKV. grid (10, 64):
//   by <  32 : K/V path (rows remapped to source batches {0,2}):
//              bx<5 -> Wk/outK else Wv/outV; col0=(bx%5)*128; row0=by*128
//   by >= 32 : Q path: Wq/outQ; col0=(bx%5)*128; row0=((by-32)*2+(bx/5))*128
//              + fused AdaIN stats pass 1 in the epilogue
// 128x128 block, BK=32, 256 threads (8 warps, each 32x64), cp.async 2-stage.
template <int MODE>
__global__ void __launch_bounds__(256) gemm_mma(
    const __nv_bfloat16* __restrict__ Ain,
    const __nv_bfloat16* __restrict__ Wk, const __nv_bfloat16* __restrict__ Wv,
    const __nv_bfloat16* __restrict__ Wq,
    const float* __restrict__ bias, const float* __restrict__ resid,
    float* __restrict__ outF,
    __nv_bfloat16* __restrict__ outK, __nv_bfloat16* __restrict__ outV,
    __nv_bfloat16* __restrict__ outQ,
    float* __restrict__ ps, float* __restrict__ pq)
{
    __shared__ __align__(16) char smem[40960];   // 2 stages x (A 10240 + B 10240)
    const uint32_t sb = smem_u32(smem);
    const int tid = threadIdx.x;
    const int w = tid >> 5, lam = tid & 31;

    const __nv_bfloat16* W;
    __nv_bfloat16* outB = nullptr;
    int row0, col0;
    bool remap = false, qpath = false;
    if (MODE == 5) {
        int bx = blockIdx.x, by = blockIdx.y;
        col0 = (bx % 5) * 128;
        if (by < 32) {
            W = (bx < 5) ? Wk : Wv;
            outB = (bx < 5) ? outK : outV;
            row0 = by * 128;
            remap = true;
        } else {
            W = Wq; outB = outQ;
            row0 = ((by - 32) * 2 + (bx / 5)) * 128;
            qpath = true;
        }
    } else {
        W = Wk;
        row0 = blockIdx.y * 128; col0 = blockIdx.x * 128;
    }

    const int warp_m = (w & 3) * 32, warp_n = (w >> 2) * 64;

    const int lrow = tid >> 1;
    const int gr = row0 + lrow;
    const int arow = remap ? ((gr & 2047) + ((gr >> 11) << 12)) : gr;
    const char* ag = (const char*)(Ain + (size_t)arow * NC) + (tid & 1) * 32;
    const char* bg = (const char*)(W + (size_t)(col0 + lrow) * NC) + (tid & 1) * 32;
    const uint32_t asb = sb + lrow * 80 + (tid & 1) * 32;
    const uint32_t bsb = sb + 10240 + lrow * 80 + (tid & 1) * 32;

    float acc[2][8][4];
#pragma unroll
    for (int i = 0; i < 2; i++)
#pragma unroll
        for (int j = 0; j < 8; j++)
#pragma unroll
            for (int e = 0; e < 4; e++) acc[i][j][e] = 0.f;

#pragma unroll
    for (int s = 0; s < 2; s++) {
        uint32_t so = s * 20480;
        int kb_ = s * 64;
        CP16(asb + so, ag + kb_); CP16(asb + so + 16, ag + kb_ + 16);
        CP16(bsb + so, bg + kb_); CP16(bsb + so + 16, bg + kb_ + 16);
        CP_COMMIT();
    }

    for (int c = 0; c < 20; c++) {
        CP_WAIT1(); __syncthreads();
        const int st = c & 1;
        const uint32_t sa  = sb + st * 20480;
        const uint32_t sbm = sb + 10240 + st * 20480;
        const uint32_t aab = sa + (warp_m + (lam & 15)) * 80 + (lam >> 4) * 16;
        const uint32_t bab4 = sbm + (warp_n + (lam & 7) + ((lam >> 4) << 3)) * 80
                              + ((lam >> 3) & 1) * 16;
#pragma unroll
        for (int s = 0; s < 2; s++) {
            uint32_t a0[4], a1[4];
            ldm_x4(a0[0], a0[1], a0[2], a0[3], aab + s * 32);
            ldm_x4(a1[0], a1[1], a1[2], a1[3], aab + 16 * 80 + s * 32);
#pragma unroll
            for (int jp = 0; jp < 4; jp++) {
                uint32_t b0, b1, b2, b3;
                ldm_x4(b0, b1, b2, b3, bab4 + jp * (16 * 80) + s * 32);
                mma_bf16(acc[0][2 * jp],     a0, b0, b1);
                mma_bf16(acc[0][2 * jp + 1], a0, b2, b3);
                mma_bf16(acc[1][2 * jp],     a1, b0, b1);
                mma_bf16(acc[1][2 * jp + 1], a1, b2, b3);
            }
        }
        __syncthreads();
        if (c + 2 < 20) {
            uint32_t so = st * 20480;
            int kb_ = (c + 2) * 64;
            CP16(asb + so, ag + kb_); CP16(asb + so + 16, ag + kb_ + 16);
            CP16(bsb + so, bg + kb_); CP16(bsb + so + 16, bg + kb_ + 16);
        }
        CP_COMMIT();
    }

    const int rb = row0 + warp_m + (lam >> 2);
    const int cb = col0 + warp_n + 2 * (lam & 3);
#pragma unroll
    for (int im = 0; im < 2; im++) {
#pragma unroll
        for (int j = 0; j < 8; j++) {
            int r = rb + im * 16;
            int cc = cb + j * 8;
            float* a4 = acc[im][j];
            if (MODE == 2) {
                size_t o0 = (size_t)r * NC + cc;
                size_t o1 = (size_t)(r + 8) * NC + cc;
                float2 rv0 = *(const float2*)(resid + o0);
                float2 rv1 = *(const float2*)(resid + o1);
                float2 bv = *(const float2*)(bias + cc);
                *(float2*)(outF + o0) = make_float2(a4[0] + bv.x + rv0.x, a4[1] + bv.y + rv0.y);
                *(float2*)(outF + o1) = make_float2(a4[2] + bv.x + rv1.x, a4[3] + bv.y + rv1.y);
            } else {
                *(uint32_t*)(outB + (size_t)r * NC + cc) = packbf(a4[0], a4[1]);
                *(uint32_t*)(outB + (size_t)(r + 8) * NC + cc) = packbf(a4[2], a4[3]);
            }
        }
    }

    // ---- fused AdaIN stats pass 1 (Q path only) ----
    if (MODE == 5 && qpath) {
        float cs[16], cq[16];
#pragma unroll
        for (int j = 0; j < 8; j++) {
            float slo = 0.f, shi = 0.f, qlo = 0.f, qhi = 0.f;
#pragma unroll
            for (int im = 0; im < 2; im++) {
                float a0 = acc[im][j][0], a1 = acc[im][j][1];
                float a2 = acc[im][j][2], a3 = acc[im][j][3];
                slo += a0 + a2;           shi += a1 + a3;
                qlo += a0 * a0 + a2 * a2; qhi += a1 * a1 + a3 * a3;
            }
#pragma unroll
            for (int off = 4; off < 32; off <<= 1) {
                slo += __shfl_xor_sync(0xffffffffu, slo, off);
                shi += __shfl_xor_sync(0xffffffffu, shi, off);
                qlo += __shfl_xor_sync(0xffffffffu, qlo, off);
                qhi += __shfl_xor_sync(0xffffffffu, qhi, off);
            }
            cs[2 * j] = slo; cs[2 * j + 1] = shi;
            cq[2 * j] = qlo; cq[2 * j + 1] = qhi;
        }
        float* sS = (float*)smem;            // [4][128]
        float* sQ = (float*)(smem + 2048);   // [4][128]
        if (lam < 4) {
#pragma unroll
            for (int j = 0; j < 8; j++) {
                int cidx = warp_n + j * 8 + 2 * lam;
                sS[(w & 3) * 128 + cidx]     = cs[2 * j];
                sS[(w & 3) * 128 + cidx + 1] = cs[2 * j + 1];
                sQ[(w & 3) * 128 + cidx]     = cq[2 * j];
                sQ[(w & 3) * 128 + cidx + 1] = cq[2 * j + 1];
            }
        }
        __syncthreads();
        if (tid < 128) {
            float S = sS[tid] + sS[128 + tid] + sS[256 + tid] + sS[384 + tid];
            float Q = sQ[tid] + sQ[128 + tid] + sQ[256 + tid] + sQ[384 + tid];
            int chunk = row0 >> 7;           // 0..63
            ps[chunk * NC + col0 + tid] = S;
            pq[chunk * NC + col0 + tid] = Q;
        }
    }
}

// ------------- AdaIN stats pass 2: warp-parallel finalize -> affine coeffs --
__global__ void __launch_bounds__(256) adain_p2(
    const float* __restrict__ ps, const float* __restrict__ pq,
    float* __restrict__ Ac, float* __restrict__ Bc)
{
    const int wg   = (blockIdx.x << 3) | (threadIdx.x >> 5);   // 0..319
    const int lane = threadIdx.x & 31;
    const int pair = wg / 160;                 // 0..1
    const int c4   = (wg % 160) * 4;
    const int bs = pair * 2, bo = bs + 1;

    float acc[16];
#pragma unroll
    for (int e = 0; e < 16; e++) acc[e] = 0.f;

    if (lane < 16) {
        int j = lane;
        float4 v;
        v = *(const float4*)(ps + (size_t)(bs * 16 + j) * NC + c4);
        acc[0] = v.x; acc[1] = v.y; acc[2] = v.z; acc[3] = v.w;
        v = *(const float4*)(pq + (size_t)(bs * 16 + j) * NC + c4);
        acc[4] = v.x; acc[5] = v.y; acc[6] = v.z; acc[7] = v.w;
        v = *(const float4*)(ps + (size_t)(bo * 16 + j) * NC + c4);
        acc[8] = v.x; acc[9] = v.y; acc[10] = v.z; acc[11] = v.w;
        v = *(const float4*)(pq + (size_t)(bo * 16 + j) * NC + c4);
        acc[12] = v.x; acc[13] = v.y; acc[14] = v.z; acc[15] = v.w;
    }
#pragma unroll
    for (int off = 16; off; off >>= 1)
#pragma unroll
        for (int e = 0; e < 16; e++)
            acc[e] += __shfl_xor_sync(0xffffffffu, acc[e], off);

    if (lane == 0) {
#pragma unroll
        for (int e = 0; e < 4; e++) {
            float Ssrc = acc[e], Qsrc = acc[4 + e];
            float Sown = acc[8 + e], Qown = acc[12 + e];
            float ms   = Ssrc / (float)NS;
            float vs   = (Qsrc - Ssrc * ms) / (float)(NS - 1);
            float sds  = sqrtf(vs + 1e-5f);
            float mo   = Sown / (float)NS;
            float vo   = (Qown - Sown * mo) / (float)(NS - 1);
            float sdo  = sqrtf(vo + 1e-5f);
            float r = sds / sdo;
            Ac[bs * NC + c4 + e] = QSCALE;
            Bc[bs * NC + c4 + e] = 0.f;
            Ac[bo * NC + c4 + e] = QSCALE * r;
            Bc[bo * NC + c4 + e] = QSCALE * (ms - mo * r);
        }
    }
}

// ---------------- Flash attention via mma.sync (split-KV = 2) ---------------
// Block: 128 q-rows of one (b,h), KV half blockIdx.z. 256 threads (8 warps).
// BK=64, 16 tiles per CTA. No-max softmax => combine is purely additive:
// each CTA writes unnormalized O (bf16) + row-sums l (fp32); attn_combine
// adds halves and normalizes. AdaIN-apply fused into Q smem staging.
// 3-stage cp.async KV pipeline with early prefetch.
__global__ void __launch_bounds__(256, 2) attn_mma(
    const __nv_bfloat16* __restrict__ q, const __nv_bfloat16* __restrict__ k,
    const __nv_bfloat16* __restrict__ v,
    __nv_bfloat16* __restrict__ os0, __nv_bfloat16* __restrict__ os1,
    float* __restrict__ l0g, float* __restrict__ l1g,
    const float* __restrict__ Ac, const float* __restrict__ Bc)
{
    extern __shared__ __align__(16) char smd[];
    // Q 128x144B @0 (18432); stage s (0..2): K @18432+s*18432, V @+9216
    const uint32_t sb = smem_u32(smd);
    const int tid = threadIdx.x, w = tid >> 5, lam = tid & 31;
    const int by = blockIdx.y;
    const int b = by / NH, h = by % NH, kb = b >> 1;
    const int q0 = blockIdx.x * 128;
    const int z = blockIdx.z;
    __nv_bfloat16* osel = z ? os1 : os0;
    float* lsel = z ? l1g : l0g;

    const size_t kv_step = (size_t)64 * NC * 2;
    const size_t z_off = (size_t)z * 16 * kv_step;   // byte offset of KV half

    const char* kg = (const char*)(k + ((size_t)kb * NS + (tid >> 2)) * NC + h * 64) + (tid & 3) * 32 + z_off;
    const char* vg = (const char*)(v + ((size_t)kb * NS + (tid >> 2)) * NC + h * 64) + (tid & 3) * 32 + z_off;
    const uint32_t ksb = sb + 18432 + (tid >> 2) * 144 + (tid & 3) * 32;
    const uint32_t vsb = ksb + 9216;

    // prologue: KV tile0 (stage0), tile1 (stage1) first (overlaps with Q work)
    CP16(ksb, kg); CP16(ksb + 16, kg + 16);
    CP16(vsb, vg); CP16(vsb + 16, vg + 16);
    CP_COMMIT();
    CP16(ksb + 18432, kg + kv_step); CP16(ksb + 18432 + 16, kg + kv_step + 16);
    CP16(vsb + 18432, vg + kv_step); CP16(vsb + 18432 + 16, vg + kv_step + 16);
    CP_COMMIT();

    // Q stage with fused AdaIN affine (x*A + B), thread: row tid>>1, half tid&1
    {
        const int row = tid >> 1, half = tid & 1;
        const uint4* qsrc = (const uint4*)((const char*)(q + ((size_t)b * NS + q0 + row) * NC + h * 64) + half * 64);
        const float* Abp = Ac + b * NC + h * 64 + half * 32;
        const float* Bbp = Bc + b * NC + h * 64 + half * 32;
        char* qdst = smd + row * 144 + half * 64;
#pragma unroll
        for (int i = 0; i < 4; i++) {
            uint4 u = qsrc[i];
            float4 A0 = *(const float4*)(Abp + i * 8);
            float4 A1 = *(const float4*)(Abp + i * 8 + 4);
            float4 B0 = *(const float4*)(Bbp + i * 8);
            float4 B1 = *(const float4*)(Bbp + i * 8 + 4);
            uint16_t* e = (uint16_t*)&u;
            uint4 ov;
            ov.x = packbf(bf2f(e[0]) * A0.x + B0.x, bf2f(e[1]) * A0.y + B0.y);
            ov.y = packbf(bf2f(e[2]) * A0.z + B0.z, bf2f(e[3]) * A0.w + B0.w);
            ov.z = packbf(bf2f(e[4]) * A1.x + B1.x, bf2f(e[5]) * A1.y + B1.y);
            ov.w = packbf(bf2f(e[6]) * A1.z + B1.z, bf2f(e[7]) * A1.w + B1.w);
            *(uint4*)(qdst + i * 16) = ov;
        }
    }
    CP_WAIT1(); __syncthreads();

    uint32_t aq[4][4];
    {
        uint32_t qab = sb + (w * 16 + (lam & 15)) * 144 + (lam >> 4) * 16;
#pragma unroll
        for (int t = 0; t < 4; t++)
            ldm_x4(aq[t][0], aq[t][1], aq[t][2], aq[t][3], qab + t * 32);
    }

    float oacc[8][4];
#pragma unroll
    for (int j = 0; j < 8; j++)
#pragma unroll
        for (int e = 0; e < 4; e++) oacc[j][e] = 0.f;
    float l0 = 0.f, l1 = 0.f;

    const uint32_t kab0 = sb + 18432 + ((lam & 7) + ((lam >> 4) << 3)) * 144
                          + ((lam >> 3) & 1) * 16;
    const uint32_t vab0 = sb + 18432 + 9216 + (lam & 15) * 144 + (lam >> 4) * 16;

    int st = 0;          // stage of current tile i
    for (int i = 0; i < 16; i++) {
        // early prefetch: tile i+2 into free stage (consumed at i-1)
        const int pf = (st + 2 >= 3) ? st - 1 : st + 2;
        if (i + 2 < 16) {
            const char* kgi = kg + (size_t)(i + 2) * kv_step;
            const char* vgi = vg + (size_t)(i + 2) * kv_step;
            uint32_t ko = ksb + pf * 18432, vo = vsb + pf * 18432;
            CP16(ko, kgi); CP16(ko + 16, kgi + 16);
            CP16(vo, vgi); CP16(vo + 16, vgi + 16);
        }
        CP_COMMIT();

        const uint32_t kab = kab0 + st * 18432;
        const uint32_t vab = vab0 + st * 18432;

        // S = Q @ K^T : c[j] covers kv cols 8j..8j+7
        float c[8][4];
#pragma unroll
        for (int j = 0; j < 8; j++)
#pragma unroll
            for (int e = 0; e < 4; e++) c[j][e] = 0.f;
#pragma unroll
        for (int t = 0; t < 4; t++) {
#pragma unroll
            for (int jp = 0; jp < 4; jp++) {
                uint32_t b0, b1, b2, b3;
                ldm_x4(b0, b1, b2, b3, kab + jp * (16 * 144) + t * 32);
                mma_bf16(c[2 * jp],     aq[t], b0, b1);
                mma_bf16(c[2 * jp + 1], aq[t], b2, b3);
            }
        }
        float p0 = 0.f, p1 = 0.f;
#pragma unroll
        for (int j = 0; j < 8; j++) {
            c[j][0] = ex2f(c[j][0]); c[j][1] = ex2f(c[j][1]);
            c[j][2] = ex2f(c[j][2]); c[j][3] = ex2f(c[j][3]);
            p0 += c[j][0] + c[j][1];
            p1 += c[j][2] + c[j][3];
        }
        l0 += p0; l1 += p1;
        uint32_t ap[4][4];
#pragma unroll
        for (int t = 0; t < 4; t++) {
            ap[t][0] = packbf(c[2*t][0],   c[2*t][1]);
            ap[t][1] = packbf(c[2*t][2],   c[2*t][3]);
            ap[t][2] = packbf(c[2*t+1][0], c[2*t+1][1]);
            ap[t][3] = packbf(c[2*t+1][2], c[2*t+1][3]);
        }
#pragma unroll
        for (int t = 0; t < 4; t++) {
#pragma unroll
            for (int jp = 0; jp < 4; jp++) {
                uint32_t b0, b1, b2, b3;
                ldm_x4t(b0, b1, b2, b3, vab + t * (16 * 144) + jp * 32);
                mma_bf16(oacc[2 * jp],     ap[t], b0, b1);
                mma_bf16(oacc[2 * jp + 1], ap[t], b2, b3);
            }
        }
        CP_WAIT1(); __syncthreads();
        st = (st + 1 >= 3) ? 0 : st + 1;
    }

    l0 += __shfl_xor_sync(0xffffffffu, l0, 1);
    l0 += __shfl_xor_sync(0xffffffffu, l0, 2);
    l1 += __shfl_xor_sync(0xffffffffu, l1, 1);
    l1 += __shfl_xor_sync(0xffffffffu, l1, 2);

    const int r = q0 + w * 16 + (lam >> 2);
    // unnormalized partial O (bf16) + l (fp32)
    __nv_bfloat16* ob0 = osel + ((size_t)b * NS + r) * NC + h * 64 + 2 * (lam & 3);
#pragma unroll
    for (int j = 0; j < 8; j++) {
        *(uint32_t*)(ob0 + j * 8)          = packbf(oacc[j][0], oacc[j][1]);
        *(uint32_t*)(ob0 + 8 * NC + j * 8) = packbf(oacc[j][2], oacc[j][3]);
    }
    if ((lam & 3) == 0) {
        lsel[(size_t)by * NS + r]     = l0;
        lsel[(size_t)by * NS + r + 8] = l1;
    }
}

// ---------------- split-KV combine: O = (O0+O1)/(l0+l1) ---------------------
__global__ void __launch_bounds__(160) attn_combine(
    const __nv_bfloat16* __restrict__ os0, const __nv_bfloat16* __restrict__ os1,
    const float* __restrict__ l0g, const float* __restrict__ l1g,
    __nv_bfloat16* __restrict__ o)
{
    int row = blockIdx.x;                   // 0..8191 = b*2048 + n
    int b = row >> 11, n = row & 2047;
    int c = threadIdx.x * 4;
    int h = c >> 6;                         // 64 % 4 == 0 -> uniform per thread
    size_t li = ((size_t)(b * NH + h)) * NS + n;
    float inv = 1.f / (l0g[li] + l1g[li]);
    size_t idx = (size_t)row * NC + c;
    uint2 u0 = *(const uint2*)(os0 + idx);
    uint2 u1 = *(const uint2*)(os1 + idx);
    const uint16_t* e0 = (const uint16_t*)&u0;
    const uint16_t* e1 = (const uint16_t*)&u1;
    uint2 ov;
    ov.x = packbf((bf2f(e0[0]) + bf2f(e1[0])) * inv, (bf2f(e0[1]) + bf2f(e1[1])) * inv);
    ov.y = packbf((bf2f(e0[2]) + bf2f(e1[2])) * inv, (bf2f(e0[3]) + bf2f(e1[3])) * inv);
    *(uint2*)(o + idx) = ov;
}

// ---------------- launch ----------------
extern "C" void kernel_launch(void* const* d_in, const int* in_sizes, int n_in,
                              void* d_out, int out_size)
{
    const float* hs = (const float*)d_in[0];
    const float* wq = (const float*)d_in[1];
    const float* wk = (const float*)d_in[2];
    const float* wv = (const float*)d_in[3];
    const float* wo = (const float*)d_in[4];
    const float* bo = (const float*)d_in[5];
    float* out = (float*)d_out;

    __nv_bfloat16 *hsb, *wqb, *wkb, *wvb, *wob, *qb, *kbp, *vbp, *obp, *os0, *os1;
    float *ps, *pq, *Ac, *Bc, *l0g, *l1g;
    cudaGetSymbolAddress((void**)&hsb, g_hsb);
    cudaGetSymbolAddress((void**)&wqb, g_wqb);
    cudaGetSymbolAddress((void**)&wkb, g_wkb);
    cudaGetSymbolAddress((void**)&wvb, g_wvb);
    cudaGetSymbolAddress((void**)&wob, g_wob);
    cudaGetSymbolAddress((void**)&qb,  g_qb);
    cudaGetSymbolAddress((void**)&kbp, g_kb);
    cudaGetSymbolAddress((void**)&vbp, g_vb);
    cudaGetSymbolAddress((void**)&obp, g_ob);
    cudaGetSymbolAddress((void**)&os0, g_os0);
    cudaGetSymbolAddress((void**)&os1, g_os1);
    cudaGetSymbolAddress((void**)&l0g, g_l0);
    cudaGetSymbolAddress((void**)&l1g, g_l1);
    cudaGetSymbolAddress((void**)&ps,  g_ps);
    cudaGetSymbolAddress((void**)&pq,  g_pq);
    cudaGetSymbolAddress((void**)&Ac,  g_A);
    cudaGetSymbolAddress((void**)&Bc,  g_B);

    const int ATTN_SMEM = 18432 + 3 * 18432;   // 73728
    cudaFuncSetAttribute(attn_mma, cudaFuncAttributeMaxDynamicSharedMemorySize, ATTN_SMEM);

    // one merged convert (hs + 4 weights)
    conv_all<<<6720, 256>>>(hs, wq, wk, wv, wo, hsb, wqb, wkb, wvb, wob);

    // merged Q + K + V projections (K/V from source batches 0,2 only)
    // + fused AdaIN stats pass 1 in the Q-path epilogue
    gemm_mma<5><<<dim3(10, 64), 256>>>(hsb, wkb, wvb, wqb, nullptr, nullptr,
                                       nullptr, kbp, vbp, qb, ps, pq);

    // AdaIN stats finalize (warp-parallel) -> affine coeffs
    adain_p2<<<40, 256>>>(ps, pq, Ac, Bc);

    // attention (split-KV = 2, additive combine) with fused AdaIN-apply on Q
    attn_mma<<<dim3(16, 40, 2), 256, ATTN_SMEM>>>(qb, kbp, vbp, os0, os1,
                                                  l0g, l1g, Ac, Bc);
    attn_combine<<<NB * NS, 160>>>(os0, os1, l0g, l1g, obp);

    // output projection + bias + residual (fp32)
    gemm_mma<2><<<dim3(5, 64), 256>>>(obp, wob, nullptr, nullptr, bo, hs,
                                      out, nullptr, nullptr, nullptr, nullptr, nullptr);
}

// round 11
// speedup vs baseline: 1.1959x; 1.0695x over previous
#include <cuda_runtime.h>
#include <cuda_bf16.h>
#include <math.h>
#include <stddef.h>
#include <stdint.h>

#define NB 4
#define NS 2048
#define NC 640
#define NH 10
#define ND 64

// log2(e) * attn_scale(0.125): folded into adain coeffs; softmax uses ex2
#define QSCALE 0.1803368801111204f

// ---------------- device scratch (no allocs allowed) ----------------
__device__ __nv_bfloat16 g_hsb[(size_t)NB * NS * NC];
__device__ __nv_bfloat16 g_wqb[NC * NC];
__device__ __nv_bfloat16 g_wkb[NC * NC];
__device__ __nv_bfloat16 g_wvb[NC * NC];
__device__ __nv_bfloat16 g_wob[NC * NC];
__device__ __nv_bfloat16 g_qb [(size_t)NB * NS * NC];   // q bf16 (raw projection)
__device__ __nv_bfloat16 g_kb [(size_t)2  * NS * NC];   // k bf16 (batches 0,2)
__device__ __nv_bfloat16 g_vb [(size_t)2  * NS * NC];
__device__ __nv_bfloat16 g_os0[(size_t)NB * NS * NC];   // split-KV partial O (half 0)
__device__ __nv_bfloat16 g_os1[(size_t)NB * NS * NC];   // split-KV partial O (half 1)
__device__ float g_l0[NB * NH * NS];                    // split-KV partial l
__device__ float g_l1[NB * NH * NS];
__device__ __nv_bfloat16 g_ob [(size_t)NB * NS * NC];   // attention out bf16
__device__ float g_ps[64 * NC];    // partial sums   (4 b x 16 chunks of 128 rows)
__device__ float g_pq[64 * NC];    // partial sq-sums
__device__ float g_A[NB * NC];     // per-(b,channel) affine scale (incl QSCALE)
__device__ float g_B[NB * NC];     // per-(b,channel) affine bias  (incl QSCALE)

// ---------------- PTX helpers (baseline sm_80+, safe on sm_100) ------------
__device__ __forceinline__ uint32_t smem_u32(const void* p) {
    uint32_t a;
    asm("{ .reg .u64 t; cvta.to.shared.u64 t, %1; cvt.u32.u64 %0, t; }" : "=r"(a) : "l"(p));
    return a;
}

#define CP16(dst, src) \
    asm volatile("cp.async.cg.shared.global [%0], [%1], 16;" :: "r"(dst), "l"(src))
#define CP_COMMIT() asm volatile("cp.async.commit_group;" ::: "memory")
#define CP_WAIT1()  asm volatile("cp.async.wait_group 1;" ::: "memory")

__device__ __forceinline__ void ldm_x4(uint32_t& r0, uint32_t& r1, uint32_t& r2, uint32_t& r3, uint32_t a) {
    asm volatile("ldmatrix.sync.aligned.m8n8.x4.shared.b16 {%0,%1,%2,%3}, [%4];"
        : "=r"(r0), "=r"(r1), "=r"(r2), "=r"(r3) : "r"(a));
}
__device__ __forceinline__ void ldm_x4t(uint32_t& r0, uint32_t& r1, uint32_t& r2, uint32_t& r3, uint32_t a) {
    asm volatile("ldmatrix.sync.aligned.m8n8.x4.trans.shared.b16 {%0,%1,%2,%3}, [%4];"
        : "=r"(r0), "=r"(r1), "=r"(r2), "=r"(r3) : "r"(a));
}
__device__ __forceinline__ void mma_bf16(float* c, const uint32_t* a,
                                         uint32_t b0, uint32_t b1) {
    asm volatile("mma.sync.aligned.m16n8k16.row.col.f32.bf16.bf16.f32 "
        "{%0,%1,%2,%3}, {%4,%5,%6,%7}, {%8,%9}, {%0,%1,%2,%3};"
        : "+f"(c[0]), "+f"(c[1]), "+f"(c[2]), "+f"(c[3])
        : "r"(a[0]), "r"(a[1]), "r"(a[2]), "r"(a[3]), "r"(b0), "r"(b1));
}
__device__ __forceinline__ uint32_t packbf(float lo, float hi) {
    __nv_bfloat162 p = __floats2bfloat162_rn(lo, hi);
    return *(uint32_t*)&p;
}
__device__ __forceinline__ float ex2f(float x) {
    float r;
    asm("ex2.approx.ftz.f32 %0, %1;" : "=f"(r) : "f"(x));
    return r;
}
__device__ __forceinline__ float bf2f(uint16_t u) {
    __nv_bfloat16 h = *(__nv_bfloat16*)&u;
    return __bfloat162float(h);
}

// ---------------- merged fp32 -> bf16 convert (hs + 4 weights) -------------
__global__ void __launch_bounds__(256) conv_all(
    const float* __restrict__ hs, const float* __restrict__ wq,
    const float* __restrict__ wk, const float* __restrict__ wv,
    const float* __restrict__ wo,
    __nv_bfloat16* __restrict__ hsb, __nv_bfloat16* __restrict__ wqb,
    __nv_bfloat16* __restrict__ wkb, __nv_bfloat16* __restrict__ wvb,
    __nv_bfloat16* __restrict__ wob)
{
    int blk = blockIdx.x;
    const float* src; __nv_bfloat16* dst; int base;
    if (blk < 5120) { src = hs; dst = hsb; base = blk; }
    else {
        int t = blk - 5120, w = t / 400;
        base = t % 400;
        src = (w == 0) ? wq : (w == 1) ? wk : (w == 2) ? wv : wo;
        dst = (w == 0) ? wqb : (w == 1) ? wkb : (w == 2) ? wvb : wob;
    }
    int i = base * 256 + threadIdx.x;
    float4 v = ((const float4*)src)[i];
    uint2 o;
    o.x = packbf(v.x, v.y);
    o.y = packbf(v.z, v.w);
    ((uint2*)dst)[i] = o;
}

// ---------------- GEMM: C[M,640] = A[M,640] @ W[640,640]^T ------------------
// 128x160 tiles (NC = 4 x 160) to fit grids into one wave:
//   MODE 5 (merged QKV): grid (4, 128) = 512 CTAs (<= 592 slots, single wave).
//     by <  32 : K  (rows remapped to source batches {0,2}); row0 = by*128
//     by <  64 : V  (remapped);                              row0 = (by-32)*128
//     by >= 64 : Q;                                          row0 = (by-64)*128
//     Q path also runs fused AdaIN stats pass 1 in the epilogue.
//   MODE 2 (out-proj + bias + residual, fp32): grid (4, 64) = 256 CTAs (1/SM).
// BK=32, 256 threads, 8 warps: warp tile 32x80 (acc 2x10x4 = 80 fp32).
// smem: 2 stages x (A 128x80B + B 160x80B) = 46080 B (static).
template <int MODE>
__global__ void __launch_bounds__(256, 2) gemm_mma(
    const __nv_bfloat16* __restrict__ Ain,
    const __nv_bfloat16* __restrict__ Wk, const __nv_bfloat16* __restrict__ Wv,
    const __nv_bfloat16* __restrict__ Wq,
    const float* __restrict__ bias, const float* __restrict__ resid,
    float* __restrict__ outF,
    __nv_bfloat16* __restrict__ outK, __nv_bfloat16* __restrict__ outV,
    __nv_bfloat16* __restrict__ outQ,
    float* __restrict__ ps, float* __restrict__ pq)
{
    __shared__ __align__(16) char smem[46080];   // 2 x (10240 A + 12800 B)
    const uint32_t sb = smem_u32(smem);
    const int tid = threadIdx.x;
    const int w = tid >> 5, lam = tid & 31;

    const __nv_bfloat16* W;
    __nv_bfloat16* outB = nullptr;
    int row0;
    const int col0 = blockIdx.x * 160;
    bool remap = false, qpath = false;
    if (MODE == 5) {
        int by = blockIdx.y;
        if (by < 32) {
            W = Wk; outB = outK; row0 = by * 128; remap = true;
        } else if (by < 64) {
            W = Wv; outB = outV; row0 = (by - 32) * 128; remap = true;
        } else {
            W = Wq; outB = outQ; row0 = (by - 64) * 128; qpath = true;
        }
    } else {
        W = Wk;
        row0 = blockIdx.y * 128;
    }

    const int warp_m = (w & 3) * 32, warp_n = (w >> 2) * 80;

    // A loader: thread t -> (row t>>1, 32B half t&1)
    const int lrow = tid >> 1;
    const int gr = row0 + lrow;
    const int arow = remap ? ((gr & 2047) + ((gr >> 11) << 12)) : gr;
    const char* ag = (const char*)(Ain + (size_t)arow * NC) + (tid & 1) * 32;
    const uint32_t asb = sb + lrow * 80 + (tid & 1) * 32;
    // B loader: 320 (row,half) pairs over 256 threads; i0 = tid, i1 = tid+256
    const int b0r = tid >> 1, b0h = (tid & 1) * 32;
    const char* bg0 = (const char*)(W + (size_t)(col0 + b0r) * NC) + b0h;
    const uint32_t bsb0 = sb + 10240 + b0r * 80 + b0h;
    const int i1 = tid + 256;
    const int b1r = i1 >> 1, b1h = (i1 & 1) * 32;
    const char* bg1 = (const char*)(W + (size_t)(col0 + b1r) * NC) + b1h;
    const uint32_t bsb1 = sb + 10240 + b1r * 80 + b1h;
    const bool has_b1 = (tid < 64);

    float acc[2][10][4];
#pragma unroll
    for (int i = 0; i < 2; i++)
#pragma unroll
        for (int j = 0; j < 10; j++)
#pragma unroll
            for (int e = 0; e < 4; e++) acc[i][j][e] = 0.f;

#pragma unroll
    for (int s = 0; s < 2; s++) {
        uint32_t so = s * 23040;
        int kb_ = s * 64;
        CP16(asb + so, ag + kb_); CP16(asb + so + 16, ag + kb_ + 16);
        CP16(bsb0 + so, bg0 + kb_); CP16(bsb0 + so + 16, bg0 + kb_ + 16);
        if (has_b1) { CP16(bsb1 + so, bg1 + kb_); CP16(bsb1 + so + 16, bg1 + kb_ + 16); }
        CP_COMMIT();
    }

    for (int c = 0; c < 20; c++) {
        CP_WAIT1(); __syncthreads();
        const int st = c & 1;
        const uint32_t sa  = sb + st * 23040;
        const uint32_t sbm = sb + 10240 + st * 23040;
        const uint32_t aab = sa + (warp_m + (lam & 15)) * 80 + (lam >> 4) * 16;
        const uint32_t bab4 = sbm + (warp_n + (lam & 7) + ((lam >> 4) << 3)) * 80
                              + ((lam >> 3) & 1) * 16;
#pragma unroll
        for (int s = 0; s < 2; s++) {
            uint32_t a0[4], a1[4];
            ldm_x4(a0[0], a0[1], a0[2], a0[3], aab + s * 32);
            ldm_x4(a1[0], a1[1], a1[2], a1[3], aab + 16 * 80 + s * 32);
#pragma unroll
            for (int jp = 0; jp < 5; jp++) {
                uint32_t b0, b1, b2, b3;
                ldm_x4(b0, b1, b2, b3, bab4 + jp * (16 * 80) + s * 32);
                mma_bf16(acc[0][2 * jp],     a0, b0, b1);
                mma_bf16(acc[0][2 * jp + 1], a0, b2, b3);
                mma_bf16(acc[1][2 * jp],     a1, b0, b1);
                mma_bf16(acc[1][2 * jp + 1], a1, b2, b3);
            }
        }
        __syncthreads();
        if (c + 2 < 20) {
            uint32_t so = st * 23040;
            int kb_ = (c + 2) * 64;
            CP16(asb + so, ag + kb_); CP16(asb + so + 16, ag + kb_ + 16);
            CP16(bsb0 + so, bg0 + kb_); CP16(bsb0 + so + 16, bg0 + kb_ + 16);
            if (has_b1) { CP16(bsb1 + so, bg1 + kb_); CP16(bsb1 + so + 16, bg1 + kb_ + 16); }
        }
        CP_COMMIT();
    }

    const int rb = row0 + warp_m + (lam >> 2);
    const int cb = col0 + warp_n + 2 * (lam & 3);
#pragma unroll
    for (int im = 0; im < 2; im++) {
#pragma unroll
        for (int j = 0; j < 10; j++) {
            int r = rb + im * 16;
            int cc = cb + j * 8;
            float* a4 = acc[im][j];
            if (MODE == 2) {
                size_t o0 = (size_t)r * NC + cc;
                size_t o1 = (size_t)(r + 8) * NC + cc;
                float2 rv0 = *(const float2*)(resid + o0);
                float2 rv1 = *(const float2*)(resid + o1);
                float2 bv = *(const float2*)(bias + cc);
                *(float2*)(outF + o0) = make_float2(a4[0] + bv.x + rv0.x, a4[1] + bv.y + rv0.y);
                *(float2*)(outF + o1) = make_float2(a4[2] + bv.x + rv1.x, a4[3] + bv.y + rv1.y);
            } else {
                *(uint32_t*)(outB + (size_t)r * NC + cc) = packbf(a4[0], a4[1]);
                *(uint32_t*)(outB + (size_t)(r + 8) * NC + cc) = packbf(a4[2], a4[3]);
            }
        }
    }

    // ---- fused AdaIN stats pass 1 (Q path only) ----
    if (MODE == 5 && qpath) {
        float cs[20], cq[20];
#pragma unroll
        for (int j = 0; j < 10; j++) {
            float slo = 0.f, shi = 0.f, qlo = 0.f, qhi = 0.f;
#pragma unroll
            for (int im = 0; im < 2; im++) {
                float a0 = acc[im][j][0], a1 = acc[im][j][1];
                float a2 = acc[im][j][2], a3 = acc[im][j][3];
                slo += a0 + a2;           shi += a1 + a3;
                qlo += a0 * a0 + a2 * a2; qhi += a1 * a1 + a3 * a3;
            }
            // reduce across the 8 row-groups of the warp (lane strides 4, 8, 16)
#pragma unroll
            for (int off = 4; off < 32; off <<= 1) {
                slo += __shfl_xor_sync(0xffffffffu, slo, off);
                shi += __shfl_xor_sync(0xffffffffu, shi, off);
                qlo += __shfl_xor_sync(0xffffffffu, qlo, off);
                qhi += __shfl_xor_sync(0xffffffffu, qhi, off);
            }
            cs[2 * j] = slo; cs[2 * j + 1] = shi;
            cq[2 * j] = qlo; cq[2 * j + 1] = qhi;
        }
        // overlay reduction buffers on stage-0 A-tile (dead after chunk 18;
        // chunk-19 reads hit stage 1 @23040+, disjoint from [0, 5120))
        float* sS = (float*)smem;            // [4][160]
        float* sQ = (float*)(smem + 2560);   // [4][160]
        if (lam < 4) {
#pragma unroll
            for (int j = 0; j < 10; j++) {
                int cidx = warp_n + j * 8 + 2 * lam;
                sS[(w & 3) * 160 + cidx]     = cs[2 * j];
                sS[(w & 3) * 160 + cidx + 1] = cs[2 * j + 1];
                sQ[(w & 3) * 160 + cidx]     = cq[2 * j];
                sQ[(w & 3) * 160 + cidx + 1] = cq[2 * j + 1];
            }
        }
        __syncthreads();
        if (tid < 160) {
            float S = sS[tid] + sS[160 + tid] + sS[320 + tid] + sS[480 + tid];
            float Q = sQ[tid] + sQ[160 + tid] + sQ[320 + tid] + sQ[480 + tid];
            int chunk = row0 >> 7;           // 0..63
            ps[chunk * NC + col0 + tid] = S;
            pq[chunk * NC + col0 + tid] = Q;
        }
    }
}

// ------------- AdaIN stats pass 2: warp-parallel finalize -> affine coeffs --
__global__ void __launch_bounds__(256) adain_p2(
    const float* __restrict__ ps, const float* __restrict__ pq,
    float* __restrict__ Ac, float* __restrict__ Bc)
{
    const int wg   = (blockIdx.x << 3) | (threadIdx.x >> 5);   // 0..319
    const int lane = threadIdx.x & 31;
    const int pair = wg / 160;                 // 0..1
    const int c4   = (wg % 160) * 4;
    const int bs = pair * 2, bo = bs + 1;

    float acc[16];
#pragma unroll
    for (int e = 0; e < 16; e++) acc[e] = 0.f;

    if (lane < 16) {
        int j = lane;
        float4 v;
        v = *(const float4*)(ps + (size_t)(bs * 16 + j) * NC + c4);
        acc[0] = v.x; acc[1] = v.y; acc[2] = v.z; acc[3] = v.w;
        v = *(const float4*)(pq + (size_t)(bs * 16 + j) * NC + c4);
        acc[4] = v.x; acc[5] = v.y; acc[6] = v.z; acc[7] = v.w;
        v = *(const float4*)(ps + (size_t)(bo * 16 + j) * NC + c4);
        acc[8] = v.x; acc[9] = v.y; acc[10] = v.z; acc[11] = v.w;
        v = *(const float4*)(pq + (size_t)(bo * 16 + j) * NC + c4);
        acc[12] = v.x; acc[13] = v.y; acc[14] = v.z; acc[15] = v.w;
    }
#pragma unroll
    for (int off = 16; off; off >>= 1)
#pragma unroll
        for (int e = 0; e < 16; e++)
            acc[e] += __shfl_xor_sync(0xffffffffu, acc[e], off);

    if (lane == 0) {
#pragma unroll
        for (int e = 0; e < 4; e++) {
            float Ssrc = acc[e], Qsrc = acc[4 + e];
            float Sown = acc[8 + e], Qown = acc[12 + e];
            float ms   = Ssrc / (float)NS;
            float vs   = (Qsrc - Ssrc * ms) / (float)(NS - 1);
            float sds  = sqrtf(vs + 1e-5f);
            float mo   = Sown / (float)NS;
            float vo   = (Qown - Sown * mo) / (float)(NS - 1);
            float sdo  = sqrtf(vo + 1e-5f);
            float r = sds / sdo;
            Ac[bs * NC + c4 + e] = QSCALE;
            Bc[bs * NC + c4 + e] = 0.f;
            Ac[bo * NC + c4 + e] = QSCALE * r;
            Bc[bo * NC + c4 + e] = QSCALE * (ms - mo * r);
        }
    }
}

// ---------------- Flash attention via mma.sync (split-KV = 2) ---------------
// Block: 128 q-rows of one (b,h), KV half blockIdx.z. 256 threads (8 warps).
// BK=64, 16 tiles per CTA. No-max softmax => combine is purely additive.
// AdaIN-apply fused into Q smem staging. 3-stage cp.async KV pipeline.
__global__ void __launch_bounds__(256, 2) attn_mma(
    const __nv_bfloat16* __restrict__ q, const __nv_bfloat16* __restrict__ k,
    const __nv_bfloat16* __restrict__ v,
    __nv_bfloat16* __restrict__ os0, __nv_bfloat16* __restrict__ os1,
    float* __restrict__ l0g, float* __restrict__ l1g,
    const float* __restrict__ Ac, const float* __restrict__ Bc)
{
    extern __shared__ __align__(16) char smd[];
    // Q 128x144B @0 (18432); stage s (0..2): K @18432+s*18432, V @+9216
    const uint32_t sb = smem_u32(smd);
    const int tid = threadIdx.x, w = tid >> 5, lam = tid & 31;
    const int by = blockIdx.y;
    const int b = by / NH, h = by % NH, kb = b >> 1;
    const int q0 = blockIdx.x * 128;
    const int z = blockIdx.z;
    __nv_bfloat16* osel = z ? os1 : os0;
    float* lsel = z ? l1g : l0g;

    const size_t kv_step = (size_t)64 * NC * 2;
    const size_t z_off = (size_t)z * 16 * kv_step;   // byte offset of KV half

    const char* kg = (const char*)(k + ((size_t)kb * NS + (tid >> 2)) * NC + h * 64) + (tid & 3) * 32 + z_off;
    const char* vg = (const char*)(v + ((size_t)kb * NS + (tid >> 2)) * NC + h * 64) + (tid & 3) * 32 + z_off;
    const uint32_t ksb = sb + 18432 + (tid >> 2) * 144 + (tid & 3) * 32;
    const uint32_t vsb = ksb + 9216;

    // prologue: KV tile0 (stage0), tile1 (stage1)
    CP16(ksb, kg); CP16(ksb + 16, kg + 16);
    CP16(vsb, vg); CP16(vsb + 16, vg + 16);
    CP_COMMIT();
    CP16(ksb + 18432, kg + kv_step); CP16(ksb + 18432 + 16, kg + kv_step + 16);
    CP16(vsb + 18432, vg + kv_step); CP16(vsb + 18432 + 16, vg + kv_step + 16);
    CP_COMMIT();

    // Q stage with fused AdaIN affine (x*A + B), thread: row tid>>1, half tid&1
    {
        const int row = tid >> 1, half = tid & 1;
        const uint4* qsrc = (const uint4*)((const char*)(q + ((size_t)b * NS + q0 + row) * NC + h * 64) + half * 64);
        const float* Abp = Ac + b * NC + h * 64 + half * 32;
        const float* Bbp = Bc + b * NC + h * 64 + half * 32;
        char* qdst = smd + row * 144 + half * 64;
#pragma unroll
        for (int i = 0; i < 4; i++) {
            uint4 u = qsrc[i];
            float4 A0 = *(const float4*)(Abp + i * 8);
            float4 A1 = *(const float4*)(Abp + i * 8 + 4);
            float4 B0 = *(const float4*)(Bbp + i * 8);
            float4 B1 = *(const float4*)(Bbp + i * 8 + 4);
            uint16_t* e = (uint16_t*)&u;
            uint4 ov;
            ov.x = packbf(bf2f(e[0]) * A0.x + B0.x, bf2f(e[1]) * A0.y + B0.y);
            ov.y = packbf(bf2f(e[2]) * A0.z + B0.z, bf2f(e[3]) * A0.w + B0.w);
            ov.z = packbf(bf2f(e[4]) * A1.x + B1.x, bf2f(e[5]) * A1.y + B1.y);
            ov.w = packbf(bf2f(e[6]) * A1.z + B1.z, bf2f(e[7]) * A1.w + B1.w);
            *(uint4*)(qdst + i * 16) = ov;
        }
    }
    CP_WAIT1(); __syncthreads();

    uint32_t aq[4][4];
    {
        uint32_t qab = sb + (w * 16 + (lam & 15)) * 144 + (lam >> 4) * 16;
#pragma unroll
        for (int t = 0; t < 4; t++)
            ldm_x4(aq[t][0], aq[t][1], aq[t][2], aq[t][3], qab + t * 32);
    }

    float oacc[8][4];
#pragma unroll
    for (int j = 0; j < 8; j++)
#pragma unroll
        for (int e = 0; e < 4; e++) oacc[j][e] = 0.f;
    float l0 = 0.f, l1 = 0.f;

    const uint32_t kab0 = sb + 18432 + ((lam & 7) + ((lam >> 4) << 3)) * 144
                          + ((lam >> 3) & 1) * 16;
    const uint32_t vab0 = sb + 18432 + 9216 + (lam & 15) * 144 + (lam >> 4) * 16;

    int st = 0;          // stage of current tile i
    for (int i = 0; i < 16; i++) {
        // early prefetch: tile i+2 into free stage (consumed at i-1)
        const int pf = (st + 2 >= 3) ? st - 1 : st + 2;
        if (i + 2 < 16) {
            const char* kgi = kg + (size_t)(i + 2) * kv_step;
            const char* vgi = vg + (size_t)(i + 2) * kv_step;
            uint32_t ko = ksb + pf * 18432, vo = vsb + pf * 18432;
            CP16(ko, kgi); CP16(ko + 16, kgi + 16);
            CP16(vo, vgi); CP16(vo + 16, vgi + 16);
        }
        CP_COMMIT();

        const uint32_t kab = kab0 + st * 18432;
        const uint32_t vab = vab0 + st * 18432;

        // S = Q @ K^T : c[j] covers kv cols 8j..8j+7
        float c[8][4];
#pragma unroll
        for (int j = 0; j < 8; j++)
#pragma unroll
            for (int e = 0; e < 4; e++) c[j][e] = 0.f;
#pragma unroll
        for (int t = 0; t < 4; t++) {
#pragma unroll
            for (int jp = 0; jp < 4; jp++) {
                uint32_t b0, b1, b2, b3;
                ldm_x4(b0, b1, b2, b3, kab + jp * (16 * 144) + t * 32);
                mma_bf16(c[2 * jp],     aq[t], b0, b1);
                mma_bf16(c[2 * jp + 1], aq[t], b2, b3);
            }
        }
        float p0 = 0.f, p1 = 0.f;
#pragma unroll
        for (int j = 0; j < 8; j++) {
            c[j][0] = ex2f(c[j][0]); c[j][1] = ex2f(c[j][1]);
            c[j][2] = ex2f(c[j][2]); c[j][3] = ex2f(c[j][3]);
            p0 += c[j][0] + c[j][1];
            p1 += c[j][2] + c[j][3];
        }
        l0 += p0; l1 += p1;
        uint32_t ap[4][4];
#pragma unroll
        for (int t = 0; t < 4; t++) {
            ap[t][0] = packbf(c[2*t][0],   c[2*t][1]);
            ap[t][1] = packbf(c[2*t][2],   c[2*t][3]);
            ap[t][2] = packbf(c[2*t+1][0], c[2*t+1][1]);
            ap[t][3] = packbf(c[2*t+1][2], c[2*t+1][3]);
        }
#pragma unroll
        for (int t = 0; t < 4; t++) {
#pragma unroll
            for (int jp = 0; jp < 4; jp++) {
                uint32_t b0, b1, b2, b3;
                ldm_x4t(b0, b1, b2, b3, vab + t * (16 * 144) + jp * 32);
                mma_bf16(oacc[2 * jp],     ap[t], b0, b1);
                mma_bf16(oacc[2 * jp + 1], ap[t], b2, b3);
            }
        }
        CP_WAIT1(); __syncthreads();
        st = (st + 1 >= 3) ? 0 : st + 1;
    }

    l0 += __shfl_xor_sync(0xffffffffu, l0, 1);
    l0 += __shfl_xor_sync(0xffffffffu, l0, 2);
    l1 += __shfl_xor_sync(0xffffffffu, l1, 1);
    l1 += __shfl_xor_sync(0xffffffffu, l1, 2);

    const int r = q0 + w * 16 + (lam >> 2);
    // unnormalized partial O (bf16) + l (fp32)
    __nv_bfloat16* ob0 = osel + ((size_t)b * NS + r) * NC + h * 64 + 2 * (lam & 3);
#pragma unroll
    for (int j = 0; j < 8; j++) {
        *(uint32_t*)(ob0 + j * 8)          = packbf(oacc[j][0], oacc[j][1]);
        *(uint32_t*)(ob0 + 8 * NC + j * 8) = packbf(oacc[j][2], oacc[j][3]);
    }
    if ((lam & 3) == 0) {
        lsel[(size_t)by * NS + r]     = l0;
        lsel[(size_t)by * NS + r + 8] = l1;
    }
}

// ---------------- split-KV combine: O = (O0+O1)/(l0+l1) ---------------------
__global__ void __launch_bounds__(160) attn_combine(
    const __nv_bfloat16* __restrict__ os0, const __nv_bfloat16* __restrict__ os1,
    const float* __restrict__ l0g, const float* __restrict__ l1g,
    __nv_bfloat16* __restrict__ o)
{
    int row = blockIdx.x;                   // 0..8191 = b*2048 + n
    int b = row >> 11, n = row & 2047;
    int c = threadIdx.x * 4;
    int h = c >> 6;                         // uniform per thread (64 % 4 == 0)
    size_t li = ((size_t)(b * NH + h)) * NS + n;
    float inv = 1.f / (l0g[li] + l1g[li]);
    size_t idx = (size_t)row * NC + c;
    uint2 u0 = *(const uint2*)(os0 + idx);
    uint2 u1 = *(const uint2*)(os1 + idx);
    const uint16_t* e0 = (const uint16_t*)&u0;
    const uint16_t* e1 = (const uint16_t*)&u1;
    uint2 ov;
    ov.x = packbf((bf2f(e0[0]) + bf2f(e1[0])) * inv, (bf2f(e0[1]) + bf2f(e1[1])) * inv);
    ov.y = packbf((bf2f(e0[2]) + bf2f(e1[2])) * inv, (bf2f(e0[3]) + bf2f(e1[3])) * inv);
    *(uint2*)(o + idx) = ov;
}

// ---------------- launch ----------------
extern "C" void kernel_launch(void* const* d_in, const int* in_sizes, int n_in,
                              void* d_out, int out_size)
{
    const float* hs = (const float*)d_in[0];
    const float* wq = (const float*)d_in[1];
    const float* wk = (const float*)d_in[2];
    const float* wv = (const float*)d_in[3];
    const float* wo = (const float*)d_in[4];
    const float* bo = (const float*)d_in[5];
    float* out = (float*)d_out;

    __nv_bfloat16 *hsb, *wqb, *wkb, *wvb, *wob, *qb, *kbp, *vbp, *obp, *os0, *os1;
    float *ps, *pq, *Ac, *Bc, *l0g, *l1g;
    cudaGetSymbolAddress((void**)&hsb, g_hsb);
    cudaGetSymbolAddress((void**)&wqb, g_wqb);
    cudaGetSymbolAddress((void**)&wkb, g_wkb);
    cudaGetSymbolAddress((void**)&wvb, g_wvb);
    cudaGetSymbolAddress((void**)&wob, g_wob);
    cudaGetSymbolAddress((void**)&qb,  g_qb);
    cudaGetSymbolAddress((void**)&kbp, g_kb);
    cudaGetSymbolAddress((void**)&vbp, g_vb);
    cudaGetSymbolAddress((void**)&obp, g_ob);
    cudaGetSymbolAddress((void**)&os0, g_os0);
    cudaGetSymbolAddress((void**)&os1, g_os1);
    cudaGetSymbolAddress((void**)&l0g, g_l0);
    cudaGetSymbolAddress((void**)&l1g, g_l1);
    cudaGetSymbolAddress((void**)&ps,  g_ps);
    cudaGetSymbolAddress((void**)&pq,  g_pq);
    cudaGetSymbolAddress((void**)&Ac,  g_A);
    cudaGetSymbolAddress((void**)&Bc,  g_B);

    const int ATTN_SMEM = 18432 + 3 * 18432;   // 73728
    cudaFuncSetAttribute(attn_mma, cudaFuncAttributeMaxDynamicSharedMemorySize, ATTN_SMEM);

    // one merged convert (hs + 4 weights)
    conv_all<<<6720, 256>>>(hs, wq, wk, wv, wo, hsb, wqb, wkb, wvb, wob);

    // merged Q + K + V projections, 128x160 tiles -> 512 CTAs (single wave)
    // + fused AdaIN stats pass 1 in the Q-path epilogue
    gemm_mma<5><<<dim3(4, 128), 256>>>(hsb, wkb, wvb, wqb, nullptr, nullptr,
                                       nullptr, kbp, vbp, qb, ps, pq);

    // AdaIN stats finalize (warp-parallel) -> affine coeffs
    adain_p2<<<40, 256>>>(ps, pq, Ac, Bc);

    // attention (split-KV = 2, additive combine) with fused AdaIN-apply on Q
    attn_mma<<<dim3(16, 40, 2), 256, ATTN_SMEM>>>(qb, kbp, vbp, os0, os1,
                                                  l0g, l1g, Ac, Bc);
    attn_combine<<<NB * NS, 160>>>(os0, os1, l0g, l1g, obp);

    // output projection + bias + residual, 128x160 tiles -> 256 CTAs (1 wave)
    gemm_mma<2><<<dim3(4, 64), 256>>>(obp, wob, nullptr, nullptr, bo, hs,
                                      out, nullptr, nullptr, nullptr, nullptr, nullptr);
}

// round 12
// speedup vs baseline: 1.2007x; 1.0040x over previous
#include <cuda_runtime.h>
#include <cuda_bf16.h>
#include <math.h>
#include <stddef.h>
#include <stdint.h>

#define NB 4
#define NS 2048
#define NC 640
#define NH 10
#define ND 64

// log2(e) * attn_scale(0.125): folded into adain coeffs; softmax uses ex2
#define QSCALE 0.1803368801111204f

// ---------------- device scratch (no allocs allowed) ----------------
__device__ __nv_bfloat16 g_hsb[(size_t)NB * NS * NC];
__device__ __nv_bfloat16 g_wqb[NC * NC];
__device__ __nv_bfloat16 g_wkb[NC * NC];
__device__ __nv_bfloat16 g_wvb[NC * NC];
__device__ __nv_bfloat16 g_wob[NC * NC];
__device__ __nv_bfloat16 g_qb [(size_t)NB * NS * NC];   // q bf16 (raw projection)
__device__ __nv_bfloat16 g_kb [(size_t)2  * NS * NC];   // k bf16 (batches 0,2)
__device__ __nv_bfloat16 g_vb [(size_t)2  * NS * NC];
__device__ __nv_bfloat16 g_os0[(size_t)NB * NS * NC];   // split-KV partial O (half 0)
__device__ __nv_bfloat16 g_os1[(size_t)NB * NS * NC];   // split-KV partial O (half 1)
__device__ float g_l0[NB * NH * NS];                    // split-KV partial l
__device__ float g_l1[NB * NH * NS];
__device__ float g_ps[64 * NC];    // partial sums   (4 b x 16 chunks of 128 rows)
__device__ float g_pq[64 * NC];    // partial sq-sums
__device__ float g_A[NB * NC];     // per-(b,channel) affine scale (incl QSCALE)
__device__ float g_B[NB * NC];     // per-(b,channel) affine bias  (incl QSCALE)

// ---------------- PTX helpers (baseline sm_80+, safe on sm_100) ------------
__device__ __forceinline__ uint32_t smem_u32(const void* p) {
    uint32_t a;
    asm("{ .reg .u64 t; cvta.to.shared.u64 t, %1; cvt.u32.u64 %0, t; }" : "=r"(a) : "l"(p));
    return a;
}

#define CP16(dst, src) \
    asm volatile("cp.async.cg.shared.global [%0], [%1], 16;" :: "r"(dst), "l"(src))
#define CP_COMMIT() asm volatile("cp.async.commit_group;" ::: "memory")
#define CP_WAIT1()  asm volatile("cp.async.wait_group 1;" ::: "memory")

__device__ __forceinline__ void ldm_x4(uint32_t& r0, uint32_t& r1, uint32_t& r2, uint32_t& r3, uint32_t a) {
    asm volatile("ldmatrix.sync.aligned.m8n8.x4.shared.b16 {%0,%1,%2,%3}, [%4];"
        : "=r"(r0), "=r"(r1), "=r"(r2), "=r"(r3) : "r"(a));
}
__device__ __forceinline__ void ldm_x4t(uint32_t& r0, uint32_t& r1, uint32_t& r2, uint32_t& r3, uint32_t a) {
    asm volatile("ldmatrix.sync.aligned.m8n8.x4.trans.shared.b16 {%0,%1,%2,%3}, [%4];"
        : "=r"(r0), "=r"(r1), "=r"(r2), "=r"(r3) : "r"(a));
}
__device__ __forceinline__ void mma_bf16(float* c, const uint32_t* a,
                                         uint32_t b0, uint32_t b1) {
    asm volatile("mma.sync.aligned.m16n8k16.row.col.f32.bf16.bf16.f32 "
        "{%0,%1,%2,%3}, {%4,%5,%6,%7}, {%8,%9}, {%0,%1,%2,%3};"
        : "+f"(c[0]), "+f"(c[1]), "+f"(c[2]), "+f"(c[3])
        : "r"(a[0]), "r"(a[1]), "r"(a[2]), "r"(a[3]), "r"(b0), "r"(b1));
}
__device__ __forceinline__ uint32_t packbf(float lo, float hi) {
    __nv_bfloat162 p = __floats2bfloat162_rn(lo, hi);
    return *(uint32_t*)&p;
}
__device__ __forceinline__ float ex2f(float x) {
    float r;
    asm("ex2.approx.ftz.f32 %0, %1;" : "=f"(r) : "f"(x));
    return r;
}
__device__ __forceinline__ float bf2f(uint16_t u) {
    __nv_bfloat16 h = *(__nv_bfloat16*)&u;
    return __bfloat162float(h);
}

// ---------------- merged fp32 -> bf16 convert (hs + 4 weights) -------------
__global__ void __launch_bounds__(256) conv_all(
    const float* __restrict__ hs, const float* __restrict__ wq,
    const float* __restrict__ wk, const float* __restrict__ wv,
    const float* __restrict__ wo,
    __nv_bfloat16* __restrict__ hsb, __nv_bfloat16* __restrict__ wqb,
    __nv_bfloat16* __restrict__ wkb, __nv_bfloat16* __restrict__ wvb,
    __nv_bfloat16* __restrict__ wob)
{
    int blk = blockIdx.x;
    const float* src; __nv_bfloat16* dst; int base;
    if (blk < 5120) { src = hs; dst = hsb; base = blk; }
    else {
        int t = blk - 5120, w = t / 400;
        base = t % 400;
        src = (w == 0) ? wq : (w == 1) ? wk : (w == 2) ? wv : wo;
        dst = (w == 0) ? wqb : (w == 1) ? wkb : (w == 2) ? wvb : wob;
    }
    int i = base * 256 + threadIdx.x;
    float4 v = ((const float4*)src)[i];
    uint2 o;
    o.x = packbf(v.x, v.y);
    o.y = packbf(v.z, v.w);
    ((uint2*)dst)[i] = o;
}

// ---------------- GEMM: C[M,640] = A[M,640] @ W[640,640]^T ------------------
// 128x160 tiles (NC = 4 x 160) to fit grids into one wave:
//   MODE 5 (merged QKV): grid (4, 128) = 512 CTAs (<= 592 slots, single wave).
//     by <  32 : K  (rows remapped to source batches {0,2}); row0 = by*128
//     by <  64 : V  (remapped);                              row0 = (by-32)*128
//     by >= 64 : Q;                                          row0 = (by-64)*128
//     Q path also runs fused AdaIN stats pass 1 in the epilogue.
//   MODE 2 (out-proj + bias + residual, fp32): grid (4, 64) = 256 CTAs.
//     A operand is the FUSED split-KV combine: (os0 + os1) / (l0 + l1),
//     computed in the A-loader (bit-identical to the former combine kernel).
//     k-chunk c covers channels [c*32, c*32+32) -> head h = c>>1 (uniform).
// BK=32, 256 threads, 8 warps: warp tile 32x80 (acc 2x10x4 = 80 fp32).
// smem: 2 stages x (A 128x80B + B 160x80B) = 46080 B (static).
template <int MODE>
__global__ void __launch_bounds__(256, 2) gemm_mma(
    const __nv_bfloat16* __restrict__ Ain,       // MODE 5: hs bf16; MODE 2: os0
    const __nv_bfloat16* __restrict__ Aos1,      // MODE 2: os1
    const float* __restrict__ l0g, const float* __restrict__ l1g,
    const __nv_bfloat16* __restrict__ Wk, const __nv_bfloat16* __restrict__ Wv,
    const __nv_bfloat16* __restrict__ Wq,
    const float* __restrict__ bias, const float* __restrict__ resid,
    float* __restrict__ outF,
    __nv_bfloat16* __restrict__ outK, __nv_bfloat16* __restrict__ outV,
    __nv_bfloat16* __restrict__ outQ,
    float* __restrict__ ps, float* __restrict__ pq)
{
    __shared__ __align__(16) char smem[46080];   // 2 x (10240 A + 12800 B)
    const uint32_t sb = smem_u32(smem);
    const int tid = threadIdx.x;
    const int w = tid >> 5, lam = tid & 31;

    const __nv_bfloat16* W;
    __nv_bfloat16* outB = nullptr;
    int row0;
    const int col0 = blockIdx.x * 160;
    bool remap = false, qpath = false;
    if (MODE == 5) {
        int by = blockIdx.y;
        if (by < 32) {
            W = Wk; outB = outK; row0 = by * 128; remap = true;
        } else if (by < 64) {
            W = Wv; outB = outV; row0 = (by - 32) * 128; remap = true;
        } else {
            W = Wq; outB = outQ; row0 = (by - 64) * 128; qpath = true;
        }
    } else {
        W = Wk;
        row0 = blockIdx.y * 128;
    }

    const int warp_m = (w & 3) * 32, warp_n = (w >> 2) * 80;

    // A loader: thread t -> (row t>>1, 32B half t&1)
    const int lrow = tid >> 1;
    const int gr = row0 + lrow;
    const int arow = remap ? ((gr & 2047) + ((gr >> 11) << 12)) : gr;
    const char* ag  = (const char*)(Ain + (size_t)arow * NC) + (tid & 1) * 32;
    const char* ag1 = (MODE == 2)
        ? (const char*)(Aos1 + (size_t)gr * NC) + (tid & 1) * 32 : nullptr;
    const uint32_t a_off = lrow * 80 + (tid & 1) * 32;   // offset within stage A region
    const uint32_t asb = sb + a_off;
    // l lookup base for MODE 2: li = (b*NH + h)*NS + n, h = chunk>>1
    const int b2 = gr >> 11, n2 = gr & 2047;
    const size_t lbase = (size_t)b2 * NH * NS + n2;
    // B loader: 320 (row,half) pairs over 256 threads; i0 = tid, i1 = tid+256
    const int b0r = tid >> 1, b0h = (tid & 1) * 32;
    const char* bg0 = (const char*)(W + (size_t)(col0 + b0r) * NC) + b0h;
    const uint32_t bsb0 = sb + 10240 + b0r * 80 + b0h;
    const int i1 = tid + 256;
    const int b1r = i1 >> 1, b1h = (i1 & 1) * 32;
    const char* bg1 = (const char*)(W + (size_t)(col0 + b1r) * NC) + b1h;
    const uint32_t bsb1 = sb + 10240 + b1r * 80 + b1h;
    const bool has_b1 = (tid < 64);

    float acc[2][10][4];
#pragma unroll
    for (int i = 0; i < 2; i++)
#pragma unroll
        for (int j = 0; j < 10; j++)
#pragma unroll
            for (int e = 0; e < 4; e++) acc[i][j][e] = 0.f;

    // ---- A chunk staging: MODE 2 does fused combine via LDG+STS ----
    auto stage_a = [&](int c, uint32_t so) {
        int kb_ = c * 64;
        if (MODE == 2) {
            uint4 u0a = *(const uint4*)(ag  + kb_);
            uint4 u0b = *(const uint4*)(ag  + kb_ + 16);
            uint4 u1a = *(const uint4*)(ag1 + kb_);
            uint4 u1b = *(const uint4*)(ag1 + kb_ + 16);
            int h = c >> 1;
            float lv = l0g[lbase + (size_t)h * NS] + l1g[lbase + (size_t)h * NS];
            float inv = 1.f / lv;
            const uint16_t* e0 = (const uint16_t*)&u0a;
            const uint16_t* f0 = (const uint16_t*)&u0b;
            const uint16_t* e1 = (const uint16_t*)&u1a;
            const uint16_t* f1 = (const uint16_t*)&u1b;
            uint4 o0, o1;
            o0.x = packbf((bf2f(e0[0]) + bf2f(e1[0])) * inv, (bf2f(e0[1]) + bf2f(e1[1])) * inv);
            o0.y = packbf((bf2f(e0[2]) + bf2f(e1[2])) * inv, (bf2f(e0[3]) + bf2f(e1[3])) * inv);
            o0.z = packbf((bf2f(e0[4]) + bf2f(e1[4])) * inv, (bf2f(e0[5]) + bf2f(e1[5])) * inv);
            o0.w = packbf((bf2f(e0[6]) + bf2f(e1[6])) * inv, (bf2f(e0[7]) + bf2f(e1[7])) * inv);
            o1.x = packbf((bf2f(f0[0]) + bf2f(f1[0])) * inv, (bf2f(f0[1]) + bf2f(f1[1])) * inv);
            o1.y = packbf((bf2f(f0[2]) + bf2f(f1[2])) * inv, (bf2f(f0[3]) + bf2f(f1[3])) * inv);
            o1.z = packbf((bf2f(f0[4]) + bf2f(f1[4])) * inv, (bf2f(f0[5]) + bf2f(f1[5])) * inv);
            o1.w = packbf((bf2f(f0[6]) + bf2f(f1[6])) * inv, (bf2f(f0[7]) + bf2f(f1[7])) * inv);
            *(uint4*)(smem + a_off + so)      = o0;
            *(uint4*)(smem + a_off + so + 16) = o1;
        } else {
            CP16(asb + so, ag + kb_); CP16(asb + so + 16, ag + kb_ + 16);
        }
    };

#pragma unroll
    for (int s = 0; s < 2; s++) {
        uint32_t so = s * 23040;
        int kb_ = s * 64;
        stage_a(s, so);
        CP16(bsb0 + so, bg0 + kb_); CP16(bsb0 + so + 16, bg0 + kb_ + 16);
        if (has_b1) { CP16(bsb1 + so, bg1 + kb_); CP16(bsb1 + so + 16, bg1 + kb_ + 16); }
        CP_COMMIT();
    }

    for (int c = 0; c < 20; c++) {
        CP_WAIT1(); __syncthreads();
        const int st = c & 1;
        const uint32_t sa  = sb + st * 23040;
        const uint32_t sbm = sb + 10240 + st * 23040;
        const uint32_t aab = sa + (warp_m + (lam & 15)) * 80 + (lam >> 4) * 16;
        const uint32_t bab4 = sbm + (warp_n + (lam & 7) + ((lam >> 4) << 3)) * 80
                              + ((lam >> 3) & 1) * 16;
#pragma unroll
        for (int s = 0; s < 2; s++) {
            uint32_t a0[4], a1[4];
            ldm_x4(a0[0], a0[1], a0[2], a0[3], aab + s * 32);
            ldm_x4(a1[0], a1[1], a1[2], a1[3], aab + 16 * 80 + s * 32);
#pragma unroll
            for (int jp = 0; jp < 5; jp++) {
                uint32_t b0, b1, b2, b3;
                ldm_x4(b0, b1, b2, b3, bab4 + jp * (16 * 80) + s * 32);
                mma_bf16(acc[0][2 * jp],     a0, b0, b1);
                mma_bf16(acc[0][2 * jp + 1], a0, b2, b3);
                mma_bf16(acc[1][2 * jp],     a1, b0, b1);
                mma_bf16(acc[1][2 * jp + 1], a1, b2, b3);
            }
        }
        __syncthreads();
        if (c + 2 < 20) {
            uint32_t so = st * 23040;
            int kb_ = (c + 2) * 64;
            stage_a(c + 2, so);
            CP16(bsb0 + so, bg0 + kb_); CP16(bsb0 + so + 16, bg0 + kb_ + 16);
            if (has_b1) { CP16(bsb1 + so, bg1 + kb_); CP16(bsb1 + so + 16, bg1 + kb_ + 16); }
        }
        CP_COMMIT();
    }

    const int rb = row0 + warp_m + (lam >> 2);
    const int cb = col0 + warp_n + 2 * (lam & 3);
#pragma unroll
    for (int im = 0; im < 2; im++) {
#pragma unroll
        for (int j = 0; j < 10; j++) {
            int r = rb + im * 16;
            int cc = cb + j * 8;
            float* a4 = acc[im][j];
            if (MODE == 2) {
                size_t o0 = (size_t)r * NC + cc;
                size_t o1 = (size_t)(r + 8) * NC + cc;
                float2 rv0 = *(const float2*)(resid + o0);
                float2 rv1 = *(const float2*)(resid + o1);
                float2 bv = *(const float2*)(bias + cc);
                *(float2*)(outF + o0) = make_float2(a4[0] + bv.x + rv0.x, a4[1] + bv.y + rv0.y);
                *(float2*)(outF + o1) = make_float2(a4[2] + bv.x + rv1.x, a4[3] + bv.y + rv1.y);
            } else {
                *(uint32_t*)(outB + (size_t)r * NC + cc) = packbf(a4[0], a4[1]);
                *(uint32_t*)(outB + (size_t)(r + 8) * NC + cc) = packbf(a4[2], a4[3]);
            }
        }
    }

    // ---- fused AdaIN stats pass 1 (Q path only) ----
    if (MODE == 5 && qpath) {
        float cs[20], cq[20];
#pragma unroll
        for (int j = 0; j < 10; j++) {
            float slo = 0.f, shi = 0.f, qlo = 0.f, qhi = 0.f;
#pragma unroll
            for (int im = 0; im < 2; im++) {
                float a0 = acc[im][j][0], a1 = acc[im][j][1];
                float a2 = acc[im][j][2], a3 = acc[im][j][3];
                slo += a0 + a2;           shi += a1 + a3;
                qlo += a0 * a0 + a2 * a2; qhi += a1 * a1 + a3 * a3;
            }
            // reduce across the 8 row-groups of the warp (lane strides 4, 8, 16)
#pragma unroll
            for (int off = 4; off < 32; off <<= 1) {
                slo += __shfl_xor_sync(0xffffffffu, slo, off);
                shi += __shfl_xor_sync(0xffffffffu, shi, off);
                qlo += __shfl_xor_sync(0xffffffffu, qlo, off);
                qhi += __shfl_xor_sync(0xffffffffu, qhi, off);
            }
            cs[2 * j] = slo; cs[2 * j + 1] = shi;
            cq[2 * j] = qlo; cq[2 * j + 1] = qhi;
        }
        // overlay reduction buffers on stage-0 A-tile (dead after chunk 18;
        // chunk-19 reads hit stage 1 @23040+, disjoint from [0, 5120))
        float* sS = (float*)smem;            // [4][160]
        float* sQ = (float*)(smem + 2560);   // [4][160]
        if (lam < 4) {
#pragma unroll
            for (int j = 0; j < 10; j++) {
                int cidx = warp_n + j * 8 + 2 * lam;
                sS[(w & 3) * 160 + cidx]     = cs[2 * j];
                sS[(w & 3) * 160 + cidx + 1] = cs[2 * j + 1];
                sQ[(w & 3) * 160 + cidx]     = cq[2 * j];
                sQ[(w & 3) * 160 + cidx + 1] = cq[2 * j + 1];
            }
        }
        __syncthreads();
        if (tid < 160) {
            float S = sS[tid] + sS[160 + tid] + sS[320 + tid] + sS[480 + tid];
            float Q = sQ[tid] + sQ[160 + tid] + sQ[320 + tid] + sQ[480 + tid];
            int chunk = row0 >> 7;           // 0..63
            ps[chunk * NC + col0 + tid] = S;
            pq[chunk * NC + col0 + tid] = Q;
        }
    }
}

// ------------- AdaIN stats pass 2: warp-parallel finalize -> affine coeffs --
__global__ void __launch_bounds__(256) adain_p2(
    const float* __restrict__ ps, const float* __restrict__ pq,
    float* __restrict__ Ac, float* __restrict__ Bc)
{
    const int wg   = (blockIdx.x << 3) | (threadIdx.x >> 5);   // 0..319
    const int lane = threadIdx.x & 31;
    const int pair = wg / 160;                 // 0..1
    const int c4   = (wg % 160) * 4;
    const int bs = pair * 2, bo = bs + 1;

    float acc[16];
#pragma unroll
    for (int e = 0; e < 16; e++) acc[e] = 0.f;

    if (lane < 16) {
        int j = lane;
        float4 v;
        v = *(const float4*)(ps + (size_t)(bs * 16 + j) * NC + c4);
        acc[0] = v.x; acc[1] = v.y; acc[2] = v.z; acc[3] = v.w;
        v = *(const float4*)(pq + (size_t)(bs * 16 + j) * NC + c4);
        acc[4] = v.x; acc[5] = v.y; acc[6] = v.z; acc[7] = v.w;
        v = *(const float4*)(ps + (size_t)(bo * 16 + j) * NC + c4);
        acc[8] = v.x; acc[9] = v.y; acc[10] = v.z; acc[11] = v.w;
        v = *(const float4*)(pq + (size_t)(bo * 16 + j) * NC + c4);
        acc[12] = v.x; acc[13] = v.y; acc[14] = v.z; acc[15] = v.w;
    }
#pragma unroll
    for (int off = 16; off; off >>= 1)
#pragma unroll
        for (int e = 0; e < 16; e++)
            acc[e] += __shfl_xor_sync(0xffffffffu, acc[e], off);

    if (lane == 0) {
#pragma unroll
        for (int e = 0; e < 4; e++) {
            float Ssrc = acc[e], Qsrc = acc[4 + e];
            float Sown = acc[8 + e], Qown = acc[12 + e];
            float ms   = Ssrc / (float)NS;
            float vs   = (Qsrc - Ssrc * ms) / (float)(NS - 1);
            float sds  = sqrtf(vs + 1e-5f);
            float mo   = Sown / (float)NS;
            float vo   = (Qown - Sown * mo) / (float)(NS - 1);
            float sdo  = sqrtf(vo + 1e-5f);
            float r = sds / sdo;
            Ac[bs * NC + c4 + e] = QSCALE;
            Bc[bs * NC + c4 + e] = 0.f;
            Ac[bo * NC + c4 + e] = QSCALE * r;
            Bc[bo * NC + c4 + e] = QSCALE * (ms - mo * r);
        }
    }
}

// ---------------- Flash attention via mma.sync (split-KV = 2) ---------------
// Block: 128 q-rows of one (b,h), KV half blockIdx.z. 256 threads (8 warps).
// BK=64, 16 tiles per CTA. No-max softmax => combine is purely additive
// (performed inside the out-proj GEMM A-loader). AdaIN-apply fused into Q
// smem staging. 3-stage cp.async KV pipeline with early prefetch.
__global__ void __launch_bounds__(256, 2) attn_mma(
    const __nv_bfloat16* __restrict__ q, const __nv_bfloat16* __restrict__ k,
    const __nv_bfloat16* __restrict__ v,
    __nv_bfloat16* __restrict__ os0, __nv_bfloat16* __restrict__ os1,
    float* __restrict__ l0g, float* __restrict__ l1g,
    const float* __restrict__ Ac, const float* __restrict__ Bc)
{
    extern __shared__ __align__(16) char smd[];
    // Q 128x144B @0 (18432); stage s (0..2): K @18432+s*18432, V @+9216
    const uint32_t sb = smem_u32(smd);
    const int tid = threadIdx.x, w = tid >> 5, lam = tid & 31;
    const int by = blockIdx.y;
    const int b = by / NH, h = by % NH, kb = b >> 1;
    const int q0 = blockIdx.x * 128;
    const int z = blockIdx.z;
    __nv_bfloat16* osel = z ? os1 : os0;
    float* lsel = z ? l1g : l0g;

    const size_t kv_step = (size_t)64 * NC * 2;
    const size_t z_off = (size_t)z * 16 * kv_step;   // byte offset of KV half

    const char* kg = (const char*)(k + ((size_t)kb * NS + (tid >> 2)) * NC + h * 64) + (tid & 3) * 32 + z_off;
    const char* vg = (const char*)(v + ((size_t)kb * NS + (tid >> 2)) * NC + h * 64) + (tid & 3) * 32 + z_off;
    const uint32_t ksb = sb + 18432 + (tid >> 2) * 144 + (tid & 3) * 32;
    const uint32_t vsb = ksb + 9216;

    // prologue: KV tile0 (stage0), tile1 (stage1)
    CP16(ksb, kg); CP16(ksb + 16, kg + 16);
    CP16(vsb, vg); CP16(vsb + 16, vg + 16);
    CP_COMMIT();
    CP16(ksb + 18432, kg + kv_step); CP16(ksb + 18432 + 16, kg + kv_step + 16);
    CP16(vsb + 18432, vg + kv_step); CP16(vsb + 18432 + 16, vg + kv_step + 16);
    CP_COMMIT();

    // Q stage with fused AdaIN affine (x*A + B), thread: row tid>>1, half tid&1
    {
        const int row = tid >> 1, half = tid & 1;
        const uint4* qsrc = (const uint4*)((const char*)(q + ((size_t)b * NS + q0 + row) * NC + h * 64) + half * 64);
        const float* Abp = Ac + b * NC + h * 64 + half * 32;
        const float* Bbp = Bc + b * NC + h * 64 + half * 32;
        char* qdst = smd + row * 144 + half * 64;
#pragma unroll
        for (int i = 0; i < 4; i++) {
            uint4 u = qsrc[i];
            float4 A0 = *(const float4*)(Abp + i * 8);
            float4 A1 = *(const float4*)(Abp + i * 8 + 4);
            float4 B0 = *(const float4*)(Bbp + i * 8);
            float4 B1 = *(const float4*)(Bbp + i * 8 + 4);
            uint16_t* e = (uint16_t*)&u;
            uint4 ov;
            ov.x = packbf(bf2f(e[0]) * A0.x + B0.x, bf2f(e[1]) * A0.y + B0.y);
            ov.y = packbf(bf2f(e[2]) * A0.z + B0.z, bf2f(e[3]) * A0.w + B0.w);
            ov.z = packbf(bf2f(e[4]) * A1.x + B1.x, bf2f(e[5]) * A1.y + B1.y);
            ov.w = packbf(bf2f(e[6]) * A1.z + B1.z, bf2f(e[7]) * A1.w + B1.w);
            *(uint4*)(qdst + i * 16) = ov;
        }
    }
    CP_WAIT1(); __syncthreads();

    uint32_t aq[4][4];
    {
        uint32_t qab = sb + (w * 16 + (lam & 15)) * 144 + (lam >> 4) * 16;
#pragma unroll
        for (int t = 0; t < 4; t++)
            ldm_x4(aq[t][0], aq[t][1], aq[t][2], aq[t][3], qab + t * 32);
    }

    float oacc[8][4];
#pragma unroll
    for (int j = 0; j < 8; j++)
#pragma unroll
        for (int e = 0; e < 4; e++) oacc[j][e] = 0.f;
    float l0 = 0.f, l1 = 0.f;

    const uint32_t kab0 = sb + 18432 + ((lam & 7) + ((lam >> 4) << 3)) * 144
                          + ((lam >> 3) & 1) * 16;
    const uint32_t vab0 = sb + 18432 + 9216 + (lam & 15) * 144 + (lam >> 4) * 16;

    int st = 0;          // stage of current tile i
    for (int i = 0; i < 16; i++) {
        // early prefetch: tile i+2 into free stage (consumed at i-1)
        const int pf = (st + 2 >= 3) ? st - 1 : st + 2;
        if (i + 2 < 16) {
            const char* kgi = kg + (size_t)(i + 2) * kv_step;
            const char* vgi = vg + (size_t)(i + 2) * kv_step;
            uint32_t ko = ksb + pf * 18432, vo = vsb + pf * 18432;
            CP16(ko, kgi); CP16(ko + 16, kgi + 16);
            CP16(vo, vgi); CP16(vo + 16, vgi + 16);
        }
        CP_COMMIT();

        const uint32_t kab = kab0 + st * 18432;
        const uint32_t vab = vab0 + st * 18432;

        // S = Q @ K^T : c[j] covers kv cols 8j..8j+7
        float c[8][4];
#pragma unroll
        for (int j = 0; j < 8; j++)
#pragma unroll
            for (int e = 0; e < 4; e++) c[j][e] = 0.f;
#pragma unroll
        for (int t = 0; t < 4; t++) {
#pragma unroll
            for (int jp = 0; jp < 4; jp++) {
                uint32_t b0, b1, b2, b3;
                ldm_x4(b0, b1, b2, b3, kab + jp * (16 * 144) + t * 32);
                mma_bf16(c[2 * jp],     aq[t], b0, b1);
                mma_bf16(c[2 * jp + 1], aq[t], b2, b3);
            }
        }
        float p0 = 0.f, p1 = 0.f;
#pragma unroll
        for (int j = 0; j < 8; j++) {
            c[j][0] = ex2f(c[j][0]); c[j][1] = ex2f(c[j][1]);
            c[j][2] = ex2f(c[j][2]); c[j][3] = ex2f(c[j][3]);
            p0 += c[j][0] + c[j][1];
            p1 += c[j][2] + c[j][3];
        }
        l0 += p0; l1 += p1;
        uint32_t ap[4][4];
#pragma unroll
        for (int t = 0; t < 4; t++) {
            ap[t][0] = packbf(c[2*t][0],   c[2*t][1]);
            ap[t][1] = packbf(c[2*t][2],   c[2*t][3]);
            ap[t][2] = packbf(c[2*t+1][0], c[2*t+1][1]);
            ap[t][3] = packbf(c[2*t+1][2], c[2*t+1][3]);
        }
#pragma unroll
        for (int t = 0; t < 4; t++) {
#pragma unroll
            for (int jp = 0; jp < 4; jp++) {
                uint32_t b0, b1, b2, b3;
                ldm_x4t(b0, b1, b2, b3, vab + t * (16 * 144) + jp * 32);
                mma_bf16(oacc[2 * jp],     ap[t], b0, b1);
                mma_bf16(oacc[2 * jp + 1], ap[t], b2, b3);
            }
        }
        CP_WAIT1(); __syncthreads();
        st = (st + 1 >= 3) ? 0 : st + 1;
    }

    l0 += __shfl_xor_sync(0xffffffffu, l0, 1);
    l0 += __shfl_xor_sync(0xffffffffu, l0, 2);
    l1 += __shfl_xor_sync(0xffffffffu, l1, 1);
    l1 += __shfl_xor_sync(0xffffffffu, l1, 2);

    const int r = q0 + w * 16 + (lam >> 2);
    // unnormalized partial O (bf16) + l (fp32)
    __nv_bfloat16* ob0 = osel + ((size_t)b * NS + r) * NC + h * 64 + 2 * (lam & 3);
#pragma unroll
    for (int j = 0; j < 8; j++) {
        *(uint32_t*)(ob0 + j * 8)          = packbf(oacc[j][0], oacc[j][1]);
        *(uint32_t*)(ob0 + 8 * NC + j * 8) = packbf(oacc[j][2], oacc[j][3]);
    }
    if ((lam & 3) == 0) {
        lsel[(size_t)by * NS + r]     = l0;
        lsel[(size_t)by * NS + r + 8] = l1;
    }
}

// ---------------- launch ----------------
extern "C" void kernel_launch(void* const* d_in, const int* in_sizes, int n_in,
                              void* d_out, int out_size)
{
    const float* hs = (const float*)d_in[0];
    const float* wq = (const float*)d_in[1];
    const float* wk = (const float*)d_in[2];
    const float* wv = (const float*)d_in[3];
    const float* wo = (const float*)d_in[4];
    const float* bo = (const float*)d_in[5];
    float* out = (float*)d_out;

    __nv_bfloat16 *hsb, *wqb, *wkb, *wvb, *wob, *qb, *kbp, *vbp, *os0, *os1;
    float *ps, *pq, *Ac, *Bc, *l0g, *l1g;
    cudaGetSymbolAddress((void**)&hsb, g_hsb);
    cudaGetSymbolAddress((void**)&wqb, g_wqb);
    cudaGetSymbolAddress((void**)&wkb, g_wkb);
    cudaGetSymbolAddress((void**)&wvb, g_wvb);
    cudaGetSymbolAddress((void**)&wob, g_wob);
    cudaGetSymbolAddress((void**)&qb,  g_qb);
    cudaGetSymbolAddress((void**)&kbp, g_kb);
    cudaGetSymbolAddress((void**)&vbp, g_vb);
    cudaGetSymbolAddress((void**)&os0, g_os0);
    cudaGetSymbolAddress((void**)&os1, g_os1);
    cudaGetSymbolAddress((void**)&l0g, g_l0);
    cudaGetSymbolAddress((void**)&l1g, g_l1);
    cudaGetSymbolAddress((void**)&ps,  g_ps);
    cudaGetSymbolAddress((void**)&pq,  g_pq);
    cudaGetSymbolAddress((void**)&Ac,  g_A);
    cudaGetSymbolAddress((void**)&Bc,  g_B);

    const int ATTN_SMEM = 18432 + 3 * 18432;   // 73728
    cudaFuncSetAttribute(attn_mma, cudaFuncAttributeMaxDynamicSharedMemorySize, ATTN_SMEM);

    // one merged convert (hs + 4 weights)
    conv_all<<<6720, 256>>>(hs, wq, wk, wv, wo, hsb, wqb, wkb, wvb, wob);

    // merged Q + K + V projections, 128x160 tiles -> 512 CTAs (single wave)
    // + fused AdaIN stats pass 1 in the Q-path epilogue
    gemm_mma<5><<<dim3(4, 128), 256>>>(hsb, nullptr, nullptr, nullptr,
                                       wkb, wvb, wqb, nullptr, nullptr,
                                       nullptr, kbp, vbp, qb, ps, pq);

    // AdaIN stats finalize (warp-parallel) -> affine coeffs
    adain_p2<<<40, 256>>>(ps, pq, Ac, Bc);

    // attention (split-KV = 2) with fused AdaIN-apply on Q
    attn_mma<<<dim3(16, 40, 2), 256, ATTN_SMEM>>>(qb, kbp, vbp, os0, os1,
                                                  l0g, l1g, Ac, Bc);

    // output projection + bias + residual, with fused split-KV combine in the
    // A-loader: A = (os0 + os1) / (l0 + l1)
    gemm_mma<2><<<dim3(4, 64), 256>>>(os0, os1, l0g, l1g,
                                      wob, nullptr, nullptr, bo, hs,
                                      out, nullptr, nullptr, nullptr, nullptr, nullptr);
}

// round 13
// speedup vs baseline: 1.2255x; 1.0207x over previous
#include <cuda_runtime.h>
#include <cuda_bf16.h>
#include <math.h>
#include <stddef.h>
#include <stdint.h>

#define NB 4
#define NS 2048
#define NC 640
#define NH 10
#define ND 64

// log2(e) * attn_scale(0.125): folded into adain coeffs; softmax uses ex2
#define QSCALE 0.1803368801111204f

// ---------------- device scratch (no allocs allowed) ----------------
__device__ __nv_bfloat16 g_hsb[(size_t)NB * NS * NC];
__device__ __nv_bfloat16 g_wqb[NC * NC];
__device__ __nv_bfloat16 g_wkb[NC * NC];
__device__ __nv_bfloat16 g_wvb[NC * NC];
__device__ __nv_bfloat16 g_wob[NC * NC];
__device__ __nv_bfloat16 g_qb [(size_t)NB * NS * NC];   // q bf16 (raw projection)
__device__ __nv_bfloat16 g_kb [(size_t)2  * NS * NC];   // k bf16 (batches 0,2)
__device__ __nv_bfloat16 g_vb [(size_t)2  * NS * NC];
__device__ __nv_bfloat16 g_os0[(size_t)NB * NS * NC];   // split-KV partial O (half 0)
__device__ __nv_bfloat16 g_os1[(size_t)NB * NS * NC];   // split-KV partial O (half 1)
__device__ float g_l0[NB * NH * NS];                    // split-KV partial l
__device__ float g_l1[NB * NH * NS];
__device__ float g_ps[64 * NC];    // partial sums   (4 b x 16 chunks of 128 rows)
__device__ float g_pq[64 * NC];    // partial sq-sums

// ---------------- PTX helpers (baseline sm_80+, safe on sm_100) ------------
__device__ __forceinline__ uint32_t smem_u32(const void* p) {
    uint32_t a;
    asm("{ .reg .u64 t; cvta.to.shared.u64 t, %1; cvt.u32.u64 %0, t; }" : "=r"(a) : "l"(p));
    return a;
}

#define CP16(dst, src) \
    asm volatile("cp.async.cg.shared.global [%0], [%1], 16;" :: "r"(dst), "l"(src))
#define CP_COMMIT() asm volatile("cp.async.commit_group;" ::: "memory")
#define CP_WAIT1()  asm volatile("cp.async.wait_group 1;" ::: "memory")

__device__ __forceinline__ void ldm_x4(uint32_t& r0, uint32_t& r1, uint32_t& r2, uint32_t& r3, uint32_t a) {
    asm volatile("ldmatrix.sync.aligned.m8n8.x4.shared.b16 {%0,%1,%2,%3}, [%4];"
        : "=r"(r0), "=r"(r1), "=r"(r2), "=r"(r3) : "r"(a));
}
__device__ __forceinline__ void ldm_x4t(uint32_t& r0, uint32_t& r1, uint32_t& r2, uint32_t& r3, uint32_t a) {
    asm volatile("ldmatrix.sync.aligned.m8n8.x4.trans.shared.b16 {%0,%1,%2,%3}, [%4];"
        : "=r"(r0), "=r"(r1), "=r"(r2), "=r"(r3) : "r"(a));
}
__device__ __forceinline__ void mma_bf16(float* c, const uint32_t* a,
                                         uint32_t b0, uint32_t b1) {
    asm volatile("mma.sync.aligned.m16n8k16.row.col.f32.bf16.bf16.f32 "
        "{%0,%1,%2,%3}, {%4,%5,%6,%7}, {%8,%9}, {%0,%1,%2,%3};"
        : "+f"(c[0]), "+f"(c[1]), "+f"(c[2]), "+f"(c[3])
        : "r"(a[0]), "r"(a[1]), "r"(a[2]), "r"(a[3]), "r"(b0), "r"(b1));
}
__device__ __forceinline__ uint32_t packbf(float lo, float hi) {
    __nv_bfloat162 p = __floats2bfloat162_rn(lo, hi);
    return *(uint32_t*)&p;
}
__device__ __forceinline__ float ex2f(float x) {
    float r;
    asm("ex2.approx.ftz.f32 %0, %1;" : "=f"(r) : "f"(x));
    return r;
}
__device__ __forceinline__ float bf2f(uint16_t u) {
    __nv_bfloat16 h = *(__nv_bfloat16*)&u;
    return __bfloat162float(h);
}

// ---------------- merged fp32 -> bf16 convert (hs + 4 weights) -------------
__global__ void __launch_bounds__(256) conv_all(
    const float* __restrict__ hs, const float* __restrict__ wq,
    const float* __restrict__ wk, const float* __restrict__ wv,
    const float* __restrict__ wo,
    __nv_bfloat16* __restrict__ hsb, __nv_bfloat16* __restrict__ wqb,
    __nv_bfloat16* __restrict__ wkb, __nv_bfloat16* __restrict__ wvb,
    __nv_bfloat16* __restrict__ wob)
{
    int blk = blockIdx.x;
    const float* src; __nv_bfloat16* dst; int base;
    if (blk < 5120) { src = hs; dst = hsb; base = blk; }
    else {
        int t = blk - 5120, w = t / 400;
        base = t % 400;
        src = (w == 0) ? wq : (w == 1) ? wk : (w == 2) ? wv : wo;
        dst = (w == 0) ? wqb : (w == 1) ? wkb : (w == 2) ? wvb : wob;
    }
    int i = base * 256 + threadIdx.x;
    float4 v = ((const float4*)src)[i];
    uint2 o;
    o.x = packbf(v.x, v.y);
    o.y = packbf(v.z, v.w);
    ((uint2*)dst)[i] = o;
}

// ---------------- QKV GEMM: 256x160 tiles, 512 threads, single wave --------
// grid (4, 64) = 256 CTAs <= 296 SMs. by<16: K (remap), by<32: V (remap),
// by>=32: Q (+ fused AdaIN stats pass 1). BK=32; 16 warps, warp tile 32x80.
// smem: 2 stages x (A 256x80B + B 160x80B) = 66560 B (dynamic).
__global__ void __launch_bounds__(512, 1) gemm_qkv(
    const __nv_bfloat16* __restrict__ Ain,
    const __nv_bfloat16* __restrict__ Wk, const __nv_bfloat16* __restrict__ Wv,
    const __nv_bfloat16* __restrict__ Wq,
    __nv_bfloat16* __restrict__ outK, __nv_bfloat16* __restrict__ outV,
    __nv_bfloat16* __restrict__ outQ,
    float* __restrict__ ps, float* __restrict__ pq)
{
    extern __shared__ __align__(16) char smem[];   // 66560
    const uint32_t sb = smem_u32(smem);
    const int tid = threadIdx.x;
    const int w = tid >> 5, lam = tid & 31;

    const __nv_bfloat16* W;
    __nv_bfloat16* outB;
    int row0;
    const int col0 = blockIdx.x * 160;
    bool remap = false, qpath = false;
    {
        int by = blockIdx.y;
        if (by < 16)      { W = Wk; outB = outK; row0 = by * 256; remap = true; }
        else if (by < 32) { W = Wv; outB = outV; row0 = (by - 16) * 256; remap = true; }
        else              { W = Wq; outB = outQ; row0 = (by - 32) * 256; qpath = true; }
    }

    const int warp_m = (w & 7) * 32, warp_n = (w >> 3) * 80;

    // A loader: thread t -> (row t>>1 of 256, 32B half t&1)
    const int lrow = tid >> 1;
    const int gr = row0 + lrow;
    const int arow = remap ? ((gr & 2047) + ((gr >> 11) << 12)) : gr;
    const char* ag = (const char*)(Ain + (size_t)arow * NC) + (tid & 1) * 32;
    const uint32_t asb = sb + lrow * 80 + (tid & 1) * 32;
    // B loader: threads 0..319 -> (row t>>1 of 160, 32B half t&1)
    const bool bld = (tid < 320);
    const int b0r = (tid >> 1) & 255, b0h = (tid & 1) * 32;
    const char* bg0 = (const char*)(W + (size_t)(col0 + (bld ? b0r : 0)) * NC) + b0h;
    const uint32_t bsb0 = sb + 20480 + b0r * 80 + b0h;

    float acc[2][10][4];
#pragma unroll
    for (int i = 0; i < 2; i++)
#pragma unroll
        for (int j = 0; j < 10; j++)
#pragma unroll
            for (int e = 0; e < 4; e++) acc[i][j][e] = 0.f;

#pragma unroll
    for (int s = 0; s < 2; s++) {
        uint32_t so = s * 33280;
        int kb_ = s * 64;
        CP16(asb + so, ag + kb_); CP16(asb + so + 16, ag + kb_ + 16);
        if (bld) { CP16(bsb0 + so, bg0 + kb_); CP16(bsb0 + so + 16, bg0 + kb_ + 16); }
        CP_COMMIT();
    }

    for (int c = 0; c < 20; c++) {
        CP_WAIT1(); __syncthreads();
        const int st = c & 1;
        const uint32_t sa  = sb + st * 33280;
        const uint32_t sbm = sa + 20480;
        const uint32_t aab = sa + (warp_m + (lam & 15)) * 80 + (lam >> 4) * 16;
        const uint32_t bab4 = sbm + (warp_n + (lam & 7) + ((lam >> 4) << 3)) * 80
                              + ((lam >> 3) & 1) * 16;
#pragma unroll
        for (int s = 0; s < 2; s++) {
            uint32_t a0[4], a1[4];
            ldm_x4(a0[0], a0[1], a0[2], a0[3], aab + s * 32);
            ldm_x4(a1[0], a1[1], a1[2], a1[3], aab + 16 * 80 + s * 32);
#pragma unroll
            for (int jp = 0; jp < 5; jp++) {
                uint32_t b0, b1, b2, b3;
                ldm_x4(b0, b1, b2, b3, bab4 + jp * (16 * 80) + s * 32);
                mma_bf16(acc[0][2 * jp],     a0, b0, b1);
                mma_bf16(acc[0][2 * jp + 1], a0, b2, b3);
                mma_bf16(acc[1][2 * jp],     a1, b0, b1);
                mma_bf16(acc[1][2 * jp + 1], a1, b2, b3);
            }
        }
        __syncthreads();
        if (c + 2 < 20) {
            uint32_t so = st * 33280;
            int kb_ = (c + 2) * 64;
            CP16(asb + so, ag + kb_); CP16(asb + so + 16, ag + kb_ + 16);
            if (bld) { CP16(bsb0 + so, bg0 + kb_); CP16(bsb0 + so + 16, bg0 + kb_ + 16); }
        }
        CP_COMMIT();
    }

    const int rb = row0 + warp_m + (lam >> 2);
    const int cb = col0 + warp_n + 2 * (lam & 3);
#pragma unroll
    for (int im = 0; im < 2; im++) {
#pragma unroll
        for (int j = 0; j < 10; j++) {
            int r = rb + im * 16;
            int cc = cb + j * 8;
            float* a4 = acc[im][j];
            *(uint32_t*)(outB + (size_t)r * NC + cc) = packbf(a4[0], a4[1]);
            *(uint32_t*)(outB + (size_t)(r + 8) * NC + cc) = packbf(a4[2], a4[3]);
        }
    }

    // ---- fused AdaIN stats pass 1 (Q path): two 128-row chunks per tile ----
    if (qpath) {
        float cs[20], cq[20];
#pragma unroll
        for (int j = 0; j < 10; j++) {
            float slo = 0.f, shi = 0.f, qlo = 0.f, qhi = 0.f;
#pragma unroll
            for (int im = 0; im < 2; im++) {
                float a0 = acc[im][j][0], a1 = acc[im][j][1];
                float a2 = acc[im][j][2], a3 = acc[im][j][3];
                slo += a0 + a2;           shi += a1 + a3;
                qlo += a0 * a0 + a2 * a2; qhi += a1 * a1 + a3 * a3;
            }
#pragma unroll
            for (int off = 4; off < 32; off <<= 1) {
                slo += __shfl_xor_sync(0xffffffffu, slo, off);
                shi += __shfl_xor_sync(0xffffffffu, shi, off);
                qlo += __shfl_xor_sync(0xffffffffu, qlo, off);
                qhi += __shfl_xor_sync(0xffffffffu, qhi, off);
            }
            cs[2 * j] = slo; cs[2 * j + 1] = shi;
            cq[2 * j] = qlo; cq[2 * j + 1] = qhi;
        }
        // overlay on stage-0 A-tile (dead after chunk 18; stage-1 @33280+)
        float* sS = (float*)smem;            // [8][160]
        float* sQ = (float*)(smem + 5120);   // [8][160]
        if (lam < 4) {
#pragma unroll
            for (int j = 0; j < 10; j++) {
                int cidx = warp_n + j * 8 + 2 * lam;
                sS[(w & 7) * 160 + cidx]     = cs[2 * j];
                sS[(w & 7) * 160 + cidx + 1] = cs[2 * j + 1];
                sQ[(w & 7) * 160 + cidx]     = cq[2 * j];
                sQ[(w & 7) * 160 + cidx + 1] = cq[2 * j + 1];
            }
        }
        __syncthreads();
        if (tid < 160) {
            float S0 = sS[tid] + sS[160 + tid] + sS[320 + tid] + sS[480 + tid];
            float S1 = sS[640 + tid] + sS[800 + tid] + sS[960 + tid] + sS[1120 + tid];
            float Q0 = sQ[tid] + sQ[160 + tid] + sQ[320 + tid] + sQ[480 + tid];
            float Q1 = sQ[640 + tid] + sQ[800 + tid] + sQ[960 + tid] + sQ[1120 + tid];
            int chunk = row0 >> 7;           // 0..62 (even)
            ps[chunk * NC + col0 + tid]       = S0;
            ps[(chunk + 1) * NC + col0 + tid] = S1;
            pq[chunk * NC + col0 + tid]       = Q0;
            pq[(chunk + 1) * NC + col0 + tid] = Q1;
        }
    }
}

// ---------------- out-proj GEMM (128x160) + fused combine + bias + resid ----
// grid (4, 64) = 256 CTAs, 2/SM -> single wave. A = (os0+os1)/(l0+l1).
__global__ void __launch_bounds__(256, 2) gemm_out(
    const __nv_bfloat16* __restrict__ Aos0, const __nv_bfloat16* __restrict__ Aos1,
    const float* __restrict__ l0g, const float* __restrict__ l1g,
    const __nv_bfloat16* __restrict__ W,
    const float* __restrict__ bias, const float* __restrict__ resid,
    float* __restrict__ outF)
{
    __shared__ __align__(16) char smem[46080];   // 2 x (10240 A + 12800 B)
    const uint32_t sb = smem_u32(smem);
    const int tid = threadIdx.x;
    const int w = tid >> 5, lam = tid & 31;
    const int row0 = blockIdx.y * 128;
    const int col0 = blockIdx.x * 160;
    const int warp_m = (w & 3) * 32, warp_n = (w >> 2) * 80;

    const int lrow = tid >> 1;
    const int gr = row0 + lrow;
    const char* ag  = (const char*)(Aos0 + (size_t)gr * NC) + (tid & 1) * 32;
    const char* ag1 = (const char*)(Aos1 + (size_t)gr * NC) + (tid & 1) * 32;
    const uint32_t a_off = lrow * 80 + (tid & 1) * 32;
    const int b2 = gr >> 11, n2 = gr & 2047;
    const size_t lbase = (size_t)b2 * NH * NS + n2;

    const int b0r = tid >> 1, b0h = (tid & 1) * 32;
    const char* bg0 = (const char*)(W + (size_t)(col0 + b0r) * NC) + b0h;
    const uint32_t bsb0 = sb + 10240 + b0r * 80 + b0h;
    const int i1 = tid + 256;
    const int b1r = i1 >> 1, b1h = (i1 & 1) * 32;
    const char* bg1 = (const char*)(W + (size_t)(col0 + b1r) * NC) + b1h;
    const uint32_t bsb1 = sb + 10240 + b1r * 80 + b1h;
    const bool has_b1 = (tid < 64);

    float acc[2][10][4];
#pragma unroll
    for (int i = 0; i < 2; i++)
#pragma unroll
        for (int j = 0; j < 10; j++)
#pragma unroll
            for (int e = 0; e < 4; e++) acc[i][j][e] = 0.f;

    auto stage_a = [&](int c, uint32_t so) {
        int kb_ = c * 64;
        uint4 u0a = *(const uint4*)(ag  + kb_);
        uint4 u0b = *(const uint4*)(ag  + kb_ + 16);
        uint4 u1a = *(const uint4*)(ag1 + kb_);
        uint4 u1b = *(const uint4*)(ag1 + kb_ + 16);
        int h = c >> 1;
        float inv = 1.f / (l0g[lbase + (size_t)h * NS] + l1g[lbase + (size_t)h * NS]);
        const uint16_t* e0 = (const uint16_t*)&u0a;
        const uint16_t* f0 = (const uint16_t*)&u0b;
        const uint16_t* e1 = (const uint16_t*)&u1a;
        const uint16_t* f1 = (const uint16_t*)&u1b;
        uint4 o0, o1;
        o0.x = packbf((bf2f(e0[0]) + bf2f(e1[0])) * inv, (bf2f(e0[1]) + bf2f(e1[1])) * inv);
        o0.y = packbf((bf2f(e0[2]) + bf2f(e1[2])) * inv, (bf2f(e0[3]) + bf2f(e1[3])) * inv);
        o0.z = packbf((bf2f(e0[4]) + bf2f(e1[4])) * inv, (bf2f(e0[5]) + bf2f(e1[5])) * inv);
        o0.w = packbf((bf2f(e0[6]) + bf2f(e1[6])) * inv, (bf2f(e0[7]) + bf2f(e1[7])) * inv);
        o1.x = packbf((bf2f(f0[0]) + bf2f(f1[0])) * inv, (bf2f(f0[1]) + bf2f(f1[1])) * inv);
        o1.y = packbf((bf2f(f0[2]) + bf2f(f1[2])) * inv, (bf2f(f0[3]) + bf2f(f1[3])) * inv);
        o1.z = packbf((bf2f(f0[4]) + bf2f(f1[4])) * inv, (bf2f(f0[5]) + bf2f(f1[5])) * inv);
        o1.w = packbf((bf2f(f0[6]) + bf2f(f1[6])) * inv, (bf2f(f0[7]) + bf2f(f1[7])) * inv);
        *(uint4*)(smem + a_off + so)      = o0;
        *(uint4*)(smem + a_off + so + 16) = o1;
    };

#pragma unroll
    for (int s = 0; s < 2; s++) {
        uint32_t so = s * 23040;
        int kb_ = s * 64;
        stage_a(s, so);
        CP16(bsb0 + so, bg0 + kb_); CP16(bsb0 + so + 16, bg0 + kb_ + 16);
        if (has_b1) { CP16(bsb1 + so, bg1 + kb_); CP16(bsb1 + so + 16, bg1 + kb_ + 16); }
        CP_COMMIT();
    }

    for (int c = 0; c < 20; c++) {
        CP_WAIT1(); __syncthreads();
        const int st = c & 1;
        const uint32_t sa  = sb + st * 23040;
        const uint32_t sbm = sa + 10240;
        const uint32_t aab = sa + (warp_m + (lam & 15)) * 80 + (lam >> 4) * 16;
        const uint32_t bab4 = sbm + (warp_n + (lam & 7) + ((lam >> 4) << 3)) * 80
                              + ((lam >> 3) & 1) * 16;
#pragma unroll
        for (int s = 0; s < 2; s++) {
            uint32_t a0[4], a1[4];
            ldm_x4(a0[0], a0[1], a0[2], a0[3], aab + s * 32);
            ldm_x4(a1[0], a1[1], a1[2], a1[3], aab + 16 * 80 + s * 32);
#pragma unroll
            for (int jp = 0; jp < 5; jp++) {
                uint32_t b0, b1, b2, b3;
                ldm_x4(b0, b1, b2, b3, bab4 + jp * (16 * 80) + s * 32);
                mma_bf16(acc[0][2 * jp],     a0, b0, b1);
                mma_bf16(acc[0][2 * jp + 1], a0, b2, b3);
                mma_bf16(acc[1][2 * jp],     a1, b0, b1);
                mma_bf16(acc[1][2 * jp + 1], a1, b2, b3);
            }
        }
        __syncthreads();
        if (c + 2 < 20) {
            uint32_t so = st * 23040;
            int kb_ = (c + 2) * 64;
            stage_a(c + 2, so);
            CP16(bsb0 + so, bg0 + kb_); CP16(bsb0 + so + 16, bg0 + kb_ + 16);
            if (has_b1) { CP16(bsb1 + so, bg1 + kb_); CP16(bsb1 + so + 16, bg1 + kb_ + 16); }
        }
        CP_COMMIT();
    }

    const int rb = row0 + warp_m + (lam >> 2);
    const int cb = col0 + warp_n + 2 * (lam & 3);
#pragma unroll
    for (int im = 0; im < 2; im++) {
#pragma unroll
        for (int j = 0; j < 10; j++) {
            int r = rb + im * 16;
            int cc = cb + j * 8;
            float* a4 = acc[im][j];
            size_t o0 = (size_t)r * NC + cc;
            size_t o1 = (size_t)(r + 8) * NC + cc;
            float2 rv0 = *(const float2*)(resid + o0);
            float2 rv1 = *(const float2*)(resid + o1);
            float2 bv = *(const float2*)(bias + cc);
            *(float2*)(outF + o0) = make_float2(a4[0] + bv.x + rv0.x, a4[1] + bv.y + rv0.y);
            *(float2*)(outF + o1) = make_float2(a4[2] + bv.x + rv1.x, a4[3] + bv.y + rv1.y);
        }
    }
}

// ---------------- Flash attention via mma.sync (split-KV = 2) ---------------
// Block: 128 q-rows of one (b,h), KV half blockIdx.z. 256 threads (8 warps).
// BK=64, 16 tiles per CTA. No-max softmax => combine additive (in gemm_out).
// AdaIN stats pass 2 fused into the prologue (from ps/pq); apply fused into
// Q smem staging. 3-stage cp.async KV pipeline with early prefetch.
__global__ void __launch_bounds__(256, 2) attn_mma(
    const __nv_bfloat16* __restrict__ q, const __nv_bfloat16* __restrict__ k,
    const __nv_bfloat16* __restrict__ v,
    __nv_bfloat16* __restrict__ os0, __nv_bfloat16* __restrict__ os1,
    float* __restrict__ l0g, float* __restrict__ l1g,
    const float* __restrict__ ps, const float* __restrict__ pq)
{
    extern __shared__ __align__(16) char smd[];
    // Q 128x144B @0 (18432); stage s (0..2): K @18432+s*18432, V @+9216;
    // AdaIN coeffs A[64], B[64] @73728 (512 B)
    const uint32_t sb = smem_u32(smd);
    const int tid = threadIdx.x, w = tid >> 5, lam = tid & 31;
    const int by = blockIdx.y;
    const int b = by / NH, h = by % NH, kb = b >> 1;
    const int q0 = blockIdx.x * 128;
    const int z = blockIdx.z;
    __nv_bfloat16* osel = z ? os1 : os0;
    float* lsel = z ? l1g : l0g;

    const size_t kv_step = (size_t)64 * NC * 2;
    const size_t z_off = (size_t)z * 16 * kv_step;   // byte offset of KV half

    const char* kg = (const char*)(k + ((size_t)kb * NS + (tid >> 2)) * NC + h * 64) + (tid & 3) * 32 + z_off;
    const char* vg = (const char*)(v + ((size_t)kb * NS + (tid >> 2)) * NC + h * 64) + (tid & 3) * 32 + z_off;
    const uint32_t ksb = sb + 18432 + (tid >> 2) * 144 + (tid & 3) * 32;
    const uint32_t vsb = ksb + 9216;

    // prologue: KV tile0 (stage0), tile1 (stage1)
    CP16(ksb, kg); CP16(ksb + 16, kg + 16);
    CP16(vsb, vg); CP16(vsb + 16, vg + 16);
    CP_COMMIT();
    CP16(ksb + 18432, kg + kv_step); CP16(ksb + 18432 + 16, kg + kv_step + 16);
    CP16(vsb + 18432, vg + kv_step); CP16(vsb + 18432 + 16, vg + kv_step + 16);
    CP_COMMIT();

    // fused AdaIN stats pass 2: per-channel affine coeffs for this (b, h)
    float* sA = (float*)(smd + 73728);
    float* sB = sA + 64;
    if (tid < 64) {
        int ch = h * 64 + tid;
        const float* pso = ps + (size_t)(b * 16) * NC + ch;
        const float* pqo = pq + (size_t)(b * 16) * NC + ch;
        float S = 0.f, Qv = 0.f;
#pragma unroll
        for (int j = 0; j < 16; j++) { S += pso[j * NC]; Qv += pqo[j * NC]; }
        float mo  = S / (float)NS;
        float vo  = (Qv - S * mo) / (float)(NS - 1);
        float sdo = sqrtf(vo + 1e-5f);
        float Acf = QSCALE, Bcf = 0.f;
        if (b & 1) {
            const float* pss = ps + (size_t)((b - 1) * 16) * NC + ch;
            const float* pqs = pq + (size_t)((b - 1) * 16) * NC + ch;
            float Ss = 0.f, Qs = 0.f;
#pragma unroll
            for (int j = 0; j < 16; j++) { Ss += pss[j * NC]; Qs += pqs[j * NC]; }
            float msf = Ss / (float)NS;
            float vs  = (Qs - Ss * msf) / (float)(NS - 1);
            float sds = sqrtf(vs + 1e-5f);
            float r = sds / sdo;
            Acf = QSCALE * r;
            Bcf = QSCALE * (msf - mo * r);
        }
        sA[tid] = Acf; sB[tid] = Bcf;
    }
    __syncthreads();

    // Q stage with fused AdaIN affine (x*A + B), thread: row tid>>1, half tid&1
    {
        const int row = tid >> 1, half = tid & 1;
        const uint4* qsrc = (const uint4*)((const char*)(q + ((size_t)b * NS + q0 + row) * NC + h * 64) + half * 64);
        const float* Abp = sA + half * 32;
        const float* Bbp = sB + half * 32;
        char* qdst = smd + row * 144 + half * 64;
#pragma unroll
        for (int i = 0; i < 4; i++) {
            uint4 u = qsrc[i];
            float4 A0 = *(const float4*)(Abp + i * 8);
            float4 A1 = *(const float4*)(Abp + i * 8 + 4);
            float4 B0 = *(const float4*)(Bbp + i * 8);
            float4 B1 = *(const float4*)(Bbp + i * 8 + 4);
            uint16_t* e = (uint16_t*)&u;
            uint4 ov;
            ov.x = packbf(bf2f(e[0]) * A0.x + B0.x, bf2f(e[1]) * A0.y + B0.y);
            ov.y = packbf(bf2f(e[2]) * A0.z + B0.z, bf2f(e[3]) * A0.w + B0.w);
            ov.z = packbf(bf2f(e[4]) * A1.x + B1.x, bf2f(e[5]) * A1.y + B1.y);
            ov.w = packbf(bf2f(e[6]) * A1.z + B1.z, bf2f(e[7]) * A1.w + B1.w);
            *(uint4*)(qdst + i * 16) = ov;
        }
    }
    CP_WAIT1(); __syncthreads();

    uint32_t aq[4][4];
    {
        uint32_t qab = sb + (w * 16 + (lam & 15)) * 144 + (lam >> 4) * 16;
#pragma unroll
        for (int t = 0; t < 4; t++)
            ldm_x4(aq[t][0], aq[t][1], aq[t][2], aq[t][3], qab + t * 32);
    }

    float oacc[8][4];
#pragma unroll
    for (int j = 0; j < 8; j++)
#pragma unroll
        for (int e = 0; e < 4; e++) oacc[j][e] = 0.f;
    float l0 = 0.f, l1 = 0.f;

    const uint32_t kab0 = sb + 18432 + ((lam & 7) + ((lam >> 4) << 3)) * 144
                          + ((lam >> 3) & 1) * 16;
    const uint32_t vab0 = sb + 18432 + 9216 + (lam & 15) * 144 + (lam >> 4) * 16;

    int st = 0;          // stage of current tile i
    for (int i = 0; i < 16; i++) {
        // early prefetch: tile i+2 into free stage (consumed at i-1)
        const int pf = (st + 2 >= 3) ? st - 1 : st + 2;
        if (i + 2 < 16) {
            const char* kgi = kg + (size_t)(i + 2) * kv_step;
            const char* vgi = vg + (size_t)(i + 2) * kv_step;
            uint32_t ko = ksb + pf * 18432, vo = vsb + pf * 18432;
            CP16(ko, kgi); CP16(ko + 16, kgi + 16);
            CP16(vo, vgi); CP16(vo + 16, vgi + 16);
        }
        CP_COMMIT();

        const uint32_t kab = kab0 + st * 18432;
        const uint32_t vab = vab0 + st * 18432;

        // S = Q @ K^T : c[j] covers kv cols 8j..8j+7
        float c[8][4];
#pragma unroll
        for (int j = 0; j < 8; j++)
#pragma unroll
            for (int e = 0; e < 4; e++) c[j][e] = 0.f;
#pragma unroll
        for (int t = 0; t < 4; t++) {
#pragma unroll
            for (int jp = 0; jp < 4; jp++) {
                uint32_t b0, b1, b2, b3;
                ldm_x4(b0, b1, b2, b3, kab + jp * (16 * 144) + t * 32);
                mma_bf16(c[2 * jp],     aq[t], b0, b1);
                mma_bf16(c[2 * jp + 1], aq[t], b2, b3);
            }
        }
        float p0 = 0.f, p1 = 0.f;
#pragma unroll
        for (int j = 0; j < 8; j++) {
            c[j][0] = ex2f(c[j][0]); c[j][1] = ex2f(c[j][1]);
            c[j][2] = ex2f(c[j][2]); c[j][3] = ex2f(c[j][3]);
            p0 += c[j][0] + c[j][1];
            p1 += c[j][2] + c[j][3];
        }
        l0 += p0; l1 += p1;
        uint32_t ap[4][4];
#pragma unroll
        for (int t = 0; t < 4; t++) {
            ap[t][0] = packbf(c[2*t][0],   c[2*t][1]);
            ap[t][1] = packbf(c[2*t][2],   c[2*t][3]);
            ap[t][2] = packbf(c[2*t+1][0], c[2*t+1][1]);
            ap[t][3] = packbf(c[2*t+1][2], c[2*t+1][3]);
        }
#pragma unroll
        for (int t = 0; t < 4; t++) {
#pragma unroll
            for (int jp = 0; jp < 4; jp++) {
                uint32_t b0, b1, b2, b3;
                ldm_x4t(b0, b1, b2, b3, vab + t * (16 * 144) + jp * 32);
                mma_bf16(oacc[2 * jp],     ap[t], b0, b1);
                mma_bf16(oacc[2 * jp + 1], ap[t], b2, b3);
            }
        }
        CP_WAIT1(); __syncthreads();
        st = (st + 1 >= 3) ? 0 : st + 1;
    }

    l0 += __shfl_xor_sync(0xffffffffu, l0, 1);
    l0 += __shfl_xor_sync(0xffffffffu, l0, 2);
    l1 += __shfl_xor_sync(0xffffffffu, l1, 1);
    l1 += __shfl_xor_sync(0xffffffffu, l1, 2);

    const int r = q0 + w * 16 + (lam >> 2);
    // unnormalized partial O (bf16) + l (fp32)
    __nv_bfloat16* ob0 = osel + ((size_t)b * NS + r) * NC + h * 64 + 2 * (lam & 3);
#pragma unroll
    for (int j = 0; j < 8; j++) {
        *(uint32_t*)(ob0 + j * 8)          = packbf(oacc[j][0], oacc[j][1]);
        *(uint32_t*)(ob0 + 8 * NC + j * 8) = packbf(oacc[j][2], oacc[j][3]);
    }
    if ((lam & 3) == 0) {
        lsel[(size_t)by * NS + r]     = l0;
        lsel[(size_t)by * NS + r + 8] = l1;
    }
}

// ---------------- launch ----------------
extern "C" void kernel_launch(void* const* d_in, const int* in_sizes, int n_in,
                              void* d_out, int out_size)
{
    const float* hs = (const float*)d_in[0];
    const float* wq = (const float*)d_in[1];
    const float* wk = (const float*)d_in[2];
    const float* wv = (const float*)d_in[3];
    const float* wo = (const float*)d_in[4];
    const float* bo = (const float*)d_in[5];
    float* out = (float*)d_out;

    __nv_bfloat16 *hsb, *wqb, *wkb, *wvb, *wob, *qb, *kbp, *vbp, *os0, *os1;
    float *ps, *pq, *l0g, *l1g;
    cudaGetSymbolAddress((void**)&hsb, g_hsb);
    cudaGetSymbolAddress((void**)&wqb, g_wqb);
    cudaGetSymbolAddress((void**)&wkb, g_wkb);
    cudaGetSymbolAddress((void**)&wvb, g_wvb);
    cudaGetSymbolAddress((void**)&wob, g_wob);
    cudaGetSymbolAddress((void**)&qb,  g_qb);
    cudaGetSymbolAddress((void**)&kbp, g_kb);
    cudaGetSymbolAddress((void**)&vbp, g_vb);
    cudaGetSymbolAddress((void**)&os0, g_os0);
    cudaGetSymbolAddress((void**)&os1, g_os1);
    cudaGetSymbolAddress((void**)&l0g, g_l0);
    cudaGetSymbolAddress((void**)&l1g, g_l1);
    cudaGetSymbolAddress((void**)&ps,  g_ps);
    cudaGetSymbolAddress((void**)&pq,  g_pq);

    const int QKV_SMEM  = 66560;
    const int ATTN_SMEM = 73728 + 512;         // + AdaIN coeff region
    cudaFuncSetAttribute(gemm_qkv, cudaFuncAttributeMaxDynamicSharedMemorySize, QKV_SMEM);
    cudaFuncSetAttribute(attn_mma, cudaFuncAttributeMaxDynamicSharedMemorySize, ATTN_SMEM);

    // one merged convert (hs + 4 weights)
    conv_all<<<6720, 256>>>(hs, wq, wk, wv, wo, hsb, wqb, wkb, wvb, wob);

    // merged Q + K + V projections, 256x160 tiles -> 256 CTAs (single wave)
    // + fused AdaIN stats pass 1 in the Q-path epilogue
    gemm_qkv<<<dim3(4, 64), 512, QKV_SMEM>>>(hsb, wkb, wvb, wqb,
                                             kbp, vbp, qb, ps, pq);

    // attention (split-KV = 2) with fused AdaIN pass 2 + apply on Q
    attn_mma<<<dim3(16, 40, 2), 256, ATTN_SMEM>>>(qb, kbp, vbp, os0, os1,
                                                  l0g, l1g, ps, pq);

    // output projection + bias + residual, with fused split-KV combine
    gemm_out<<<dim3(4, 64), 256>>>(os0, os1, l0g, l1g, wob, bo, hs, out);
}